// round 1
// baseline (speedup 1.0000x reference)
#include <cuda_runtime.h>

#define NN 50000
#define EE 800000
#define FIN 128
#define HID 32
#define NHEADS 8
#define H1 256
#define NUM_WALKS 512
#define WALK_LEN 64
#define WINDOW 5
#define NEG_S 10
#define NEG_SLOPE 0.2f
#define INV_TEMP (1.0f/0.07f)

// ---------------- scratch (device globals; no cudaMalloc allowed) ----------
__device__ float g_xw1[(size_t)NN * H1];
__device__ float g_emb1[(size_t)NN * H1];
__device__ float g_xw2[(size_t)NN * H1];
__device__ float g_emb2[(size_t)NN * H1];
__device__ float g_als1[NN * NHEADS];
__device__ float g_ald1[NN * NHEADS];
__device__ float g_als2[NN];
__device__ float g_ald2[NN];
__device__ float g_inv[NN];
__device__ int   g_deg[NN];
__device__ int   g_rowptr[NN + 1];
__device__ int   g_wptr[NN];
__device__ int   g_col[EE];
__device__ float g_terms[NUM_WALKS * WALK_LEN];

// ---------------- CSR build ------------------------------------------------
__global__ void k_zero_deg() {
    int i = blockIdx.x * blockDim.x + threadIdx.x;
    if (i < NN) g_deg[i] = 0;
}

__global__ void k_count(const int* __restrict__ edge_index) {
    int e = blockIdx.x * blockDim.x + threadIdx.x;
    if (e < EE) {
        int dst = edge_index[EE + e];
        atomicAdd(&g_deg[dst], 1);
    }
}

__global__ void k_scan() {   // single block, 1024 threads: exclusive scan of deg
    __shared__ int sh[1024];
    __shared__ int carry_s;
    int tid = threadIdx.x;
    if (tid == 0) carry_s = 0;
    __syncthreads();
    for (int base = 0; base < NN; base += 1024) {
        int i = base + tid;
        int v = (i < NN) ? g_deg[i] : 0;
        sh[tid] = v;
        __syncthreads();
        for (int off = 1; off < 1024; off <<= 1) {
            int t = (tid >= off) ? sh[tid - off] : 0;
            __syncthreads();
            sh[tid] += t;
            __syncthreads();
        }
        int carry = carry_s;
        int exc = carry + sh[tid] - v;
        if (i < NN) { g_rowptr[i] = exc; g_wptr[i] = exc; }
        __syncthreads();
        if (tid == 0) carry_s = carry + sh[1023];
        __syncthreads();
    }
    if (tid == 0) g_rowptr[NN] = carry_s;
}

__global__ void k_scatter(const int* __restrict__ edge_index) {
    int e = blockIdx.x * blockDim.x + threadIdx.x;
    if (e < EE) {
        int src = edge_index[e];
        int dst = edge_index[EE + e];
        int pos = atomicAdd(&g_wptr[dst], 1);
        g_col[pos] = src;
    }
}

// ---------------- SGEMM: C[M,256] = A[M,K] * B[K,256]  (fp32, FFMA2) -------
// 128x128 block tile, BK=8, 256 threads, 8x8 per thread with f32x2 packed acc.
__global__ __launch_bounds__(256, 2)
void k_sgemm(const float* __restrict__ A, const float* __restrict__ B,
             float* __restrict__ C, int M, int K)
{
    __shared__ float As[8][128];
    __shared__ float Bs[8][128];
    const int N2 = 256;
    int tid = threadIdx.x;
    int tx = tid & 15, ty = tid >> 4;
    int rBase = blockIdx.x * 128;
    int cBase = blockIdx.y * 128;

    unsigned long long acc[4][8];
#pragma unroll
    for (int i = 0; i < 4; i++)
#pragma unroll
        for (int j = 0; j < 8; j++) acc[i][j] = 0ULL;

    int arow = tid >> 1;
    int acol = (tid & 1) * 4;
    int brow = tid >> 5;
    int bcol = (tid & 31) * 4;

    for (int k0 = 0; k0 < K; k0 += 8) {
        float4 av = make_float4(0.f, 0.f, 0.f, 0.f);
        int gr = rBase + arow;
        if (gr < M) av = *(const float4*)(A + (size_t)gr * K + k0 + acol);
        As[acol + 0][arow] = av.x;
        As[acol + 1][arow] = av.y;
        As[acol + 2][arow] = av.z;
        As[acol + 3][arow] = av.w;
        float4 bv = *(const float4*)(B + (size_t)(k0 + brow) * N2 + cBase + bcol);
        *(float4*)&Bs[brow][bcol] = bv;
        __syncthreads();
#pragma unroll
        for (int k = 0; k < 8; k++) {
            float4 a0 = *(float4*)&As[k][ty * 8];
            float4 a4 = *(float4*)&As[k][ty * 8 + 4];
            float4 b0 = *(float4*)&Bs[k][tx * 8];
            float4 b4 = *(float4*)&Bs[k][tx * 8 + 4];
            unsigned long long ar[4];
            asm("mov.b64 %0, {%1,%2};" : "=l"(ar[0]) : "r"(__float_as_uint(a0.x)), "r"(__float_as_uint(a0.y)));
            asm("mov.b64 %0, {%1,%2};" : "=l"(ar[1]) : "r"(__float_as_uint(a0.z)), "r"(__float_as_uint(a0.w)));
            asm("mov.b64 %0, {%1,%2};" : "=l"(ar[2]) : "r"(__float_as_uint(a4.x)), "r"(__float_as_uint(a4.y)));
            asm("mov.b64 %0, {%1,%2};" : "=l"(ar[3]) : "r"(__float_as_uint(a4.z)), "r"(__float_as_uint(a4.w)));
            float bs[8] = {b0.x, b0.y, b0.z, b0.w, b4.x, b4.y, b4.z, b4.w};
            unsigned long long bb[8];
#pragma unroll
            for (int j = 0; j < 8; j++) {
                unsigned r = __float_as_uint(bs[j]);
                asm("mov.b64 %0, {%1,%1};" : "=l"(bb[j]) : "r"(r));
            }
#pragma unroll
            for (int i = 0; i < 4; i++)
#pragma unroll
                for (int j = 0; j < 8; j++)
                    asm("fma.rn.f32x2 %0, %1, %2, %0;" : "+l"(acc[i][j]) : "l"(ar[i]), "l"(bb[j]));
        }
        __syncthreads();
    }
#pragma unroll
    for (int i = 0; i < 4; i++) {
        int r0 = rBase + ty * 8 + 2 * i;
#pragma unroll
        for (int j = 0; j < 8; j++) {
            int c = cBase + tx * 8 + j;
            float lo = __uint_as_float((unsigned)(acc[i][j] & 0xffffffffULL));
            float hi = __uint_as_float((unsigned)(acc[i][j] >> 32));
            if (r0 < M)     C[(size_t)r0 * N2 + c] = lo;
            if (r0 + 1 < M) C[(size_t)(r0 + 1) * N2 + c] = hi;
        }
    }
}

// ---------------- attention logits per node: al_s, al_d --------------------
template<int H, int C>
__global__ void k_al(const float* __restrict__ xw, const float* __restrict__ a_src,
                     const float* __restrict__ a_dst,
                     float* __restrict__ als, float* __restrict__ ald)
{
    int gw = (blockIdx.x * blockDim.x + threadIdx.x) >> 5;
    int lane = threadIdx.x & 31;
    if (gw >= NN * H) return;
    int n = gw / H, h = gw % H;
    const float* row = xw + (size_t)n * (H * C) + h * C;
    float s = 0.f, d = 0.f;
    for (int c = lane; c < C; c += 32) {
        float v = row[c];
        s += v * a_src[h * C + c];
        d += v * a_dst[h * C + c];
    }
    for (int o = 16; o; o >>= 1) {
        s += __shfl_down_sync(0xffffffffu, s, o);
        d += __shfl_down_sync(0xffffffffu, d, o);
    }
    if (lane == 0) { als[n * H + h] = s; ald[n * H + h] = d; }
}

// ---------------- per-dst softmax aggregation (block per node) -------------
template<int H, bool ELU>
__global__ __launch_bounds__(256)
void k_agg(const float* __restrict__ xw, const float* __restrict__ als,
           const float* __restrict__ ald, const float* __restrict__ bias,
           float* __restrict__ out)
{
    constexpr int CAP = 64;
    constexpr int WPH = 8 / H;          // warps per head
    constexpr int CPH = 256 / H;        // channels per head
    __shared__ int   col_s[CAP];
    __shared__ float ex_s[CAP * H];
    __shared__ float maxv[H], den[H], esh[H], aldsh[H], exself[H];
    __shared__ float wred[8];

    int n = blockIdx.x;
    int tid = threadIdx.x, lane = tid & 31, w = tid >> 5;
    int beg = g_rowptr[n];
    int deg = g_rowptr[n + 1] - beg;

    if (tid < H) {
        float as = als[n * H + tid], ad = ald[n * H + tid];
        aldsh[tid] = ad;
        float e = as + ad;
        e = e > 0.f ? e : NEG_SLOPE * e;
        esh[tid] = e;
    }
    __syncthreads();

    int h = w % H;
    int sub = w / H;
    float ad_h = aldsh[h];

    // pass 1: per-head max over neighbors (streaming)
    float lm = -1e30f;
    for (int j = sub * 32 + lane; j < deg; j += 32 * WPH) {
        int src = g_col[beg + j];
        float e = als[src * H + h] + ad_h;
        e = e > 0.f ? e : NEG_SLOPE * e;
        lm = fmaxf(lm, e);
    }
    for (int o = 16; o; o >>= 1) lm = fmaxf(lm, __shfl_xor_sync(0xffffffffu, lm, o));
    if (lane == 0) wred[w] = lm;
    __syncthreads();
    if (tid < H) {
        float m = esh[tid];
        for (int s = 0; s < WPH; s++) m = fmaxf(m, wred[tid + s * H]);
        maxv[tid] = m;
        float exs = expf(esh[tid] - m);
        exself[tid] = exs;
        den[tid] = exs;
    }
    __syncthreads();

    int hc = tid / CPH;
    float acc = exself[hc] * xw[(size_t)n * 256 + tid];
    float mh = maxv[h];

    for (int c0 = 0; c0 < deg; c0 += CAP) {
        int cn = min(CAP, deg - c0);
        __syncthreads();
        for (int j = tid; j < cn; j += 256) col_s[j] = g_col[beg + c0 + j];
        __syncthreads();
        float dsum = 0.f;
        for (int j = sub * 32 + lane; j < cn; j += 32 * WPH) {
            int src = col_s[j];
            float e = als[src * H + h] + ad_h;
            e = e > 0.f ? e : NEG_SLOPE * e;
            float ex = expf(e - mh);
            ex_s[j * H + h] = ex;
            dsum += ex;
        }
        for (int o = 16; o; o >>= 1) dsum += __shfl_xor_sync(0xffffffffu, dsum, o);
        if (lane == 0) wred[w] = dsum;
        __syncthreads();
        if (tid < H) {
            float d = 0.f;
            for (int s = 0; s < WPH; s++) d += wred[tid + s * H];
            den[tid] += d;
        }
#pragma unroll 4
        for (int j = 0; j < cn; j++)
            acc += ex_s[j * H + hc] * xw[(size_t)col_s[j] * 256 + tid];
    }
    __syncthreads();
    float o = acc / den[hc] + bias[tid];
    if (ELU) o = o > 0.f ? o : expm1f(o);
    out[(size_t)n * 256 + tid] = o;
}

// ---------------- inverse norms of concat(emb1, emb2) ----------------------
__global__ void k_norm()
{
    int gw = (blockIdx.x * blockDim.x + threadIdx.x) >> 5;
    int lane = threadIdx.x & 31;
    if (gw >= NN) return;
    const float4* r1 = (const float4*)(g_emb1 + (size_t)gw * 256);
    const float4* r2 = (const float4*)(g_emb2 + (size_t)gw * 256);
    float s = 0.f;
    for (int i = lane; i < 64; i += 32) {
        float4 v = r1[i]; s += v.x * v.x + v.y * v.y + v.z * v.z + v.w * v.w;
        float4 u = r2[i]; s += u.x * u.x + u.y * u.y + u.z * u.z + u.w * u.w;
    }
    for (int o = 16; o; o >>= 1) s += __shfl_xor_sync(0xffffffffu, s, o);
    if (lane == 0) g_inv[gw] = 1.f / fmaxf(sqrtf(s), 1e-8f);
}

// ---------------- contrastive loss (warp per anchor) -----------------------
__device__ __forceinline__ float dot512(const float4& a0, const float4& a1,
                                        const float4& a2, const float4& a3,
                                        int pn, int lane)
{
    const float4 p0 = *(const float4*)(g_emb1 + (size_t)pn * 256 + lane * 8);
    const float4 p1 = *(const float4*)(g_emb1 + (size_t)pn * 256 + lane * 8 + 4);
    const float4 p2 = *(const float4*)(g_emb2 + (size_t)pn * 256 + lane * 8);
    const float4 p3 = *(const float4*)(g_emb2 + (size_t)pn * 256 + lane * 8 + 4);
    float s = a0.x * p0.x + a0.y * p0.y + a0.z * p0.z + a0.w * p0.w
            + a1.x * p1.x + a1.y * p1.y + a1.z * p1.z + a1.w * p1.w
            + a2.x * p2.x + a2.y * p2.y + a2.z * p2.z + a2.w * p2.w
            + a3.x * p3.x + a3.y * p3.y + a3.z * p3.z + a3.w * p3.w;
    for (int o = 16; o; o >>= 1) s += __shfl_xor_sync(0xffffffffu, s, o);
    return s;   // full sum in all lanes
}

__global__ void k_loss(const int* __restrict__ walks, const int* __restrict__ negs)
{
    int gw = (blockIdx.x * blockDim.x + threadIdx.x) >> 5;
    int lane = threadIdx.x & 31;
    if (gw >= NUM_WALKS * WALK_LEN) return;
    int b = gw >> 6, l = gw & 63;
    int a = walks[gw];
    float ainv = g_inv[a];
    const float4 a0 = *(const float4*)(g_emb1 + (size_t)a * 256 + lane * 8);
    const float4 a1 = *(const float4*)(g_emb1 + (size_t)a * 256 + lane * 8 + 4);
    const float4 a2 = *(const float4*)(g_emb2 + (size_t)a * 256 + lane * 8);
    const float4 a3 = *(const float4*)(g_emb2 + (size_t)a * 256 + lane * 8 + 4);

    int posn[2 * WINDOW];
    bool pvalid[2 * WINDOW];
#pragma unroll
    for (int p = 0; p < 2 * WINDOW; p++) {
        int off = (p < WINDOW) ? (p - WINDOW) : (p - WINDOW + 1);
        int pp = l + off;
        bool v = (pp >= 0) && (pp < WALK_LEN);
        pvalid[p] = v;
        int ppc = min(max(pp, 0), WALK_LEN - 1);
        posn[p] = walks[(b << 6) + ppc];
    }
    float pos_sum = 0.f;
#pragma unroll
    for (int p = 0; p < 2 * WINDOW; p++) {
        int pn = posn[p];
        float d = dot512(a0, a1, a2, a3, pn, lane);
        float sim = d * ainv * g_inv[pn] * INV_TEMP;
        if (pvalid[p]) pos_sum += expf(sim);
    }
    float neg_sum = 0.f;
#pragma unroll
    for (int s = 0; s < NEG_S; s++) {
        int ng = negs[gw * NEG_S + s];
        bool inpos = false;
#pragma unroll
        for (int p = 0; p < 2 * WINDOW; p++)
            inpos = inpos || (pvalid[p] && (ng == posn[p]));
        float d = dot512(a0, a1, a2, a3, ng, lane);
        float sim = d * ainv * g_inv[ng] * INV_TEMP;
        if (!inpos) neg_sum += expf(sim);
    }
    float term = log1pf(neg_sum / pos_sum);   // == -log(pos/(pos+neg)); has_pos always true for L=64,W=5
    if (lane == 0) g_terms[gw] = term;
}

__global__ void k_reduce(float* __restrict__ out)
{
    __shared__ float sh[1024];
    int tid = threadIdx.x;
    float s = 0.f;
    for (int i = tid; i < NUM_WALKS * WALK_LEN; i += 1024) s += g_terms[i];
    sh[tid] = s;
    __syncthreads();
    for (int o = 512; o; o >>= 1) {
        if (tid < o) sh[tid] += sh[tid + o];
        __syncthreads();
    }
    if (tid == 0) out[0] = sh[0];
}

// ---------------- driver ---------------------------------------------------
extern "C" void kernel_launch(void* const* d_in, const int* in_sizes, int n_in,
                              void* d_out, int out_size)
{
    const float* x          = (const float*)d_in[0];
    const int*   edge_index = (const int*)  d_in[1];
    const int*   walks      = (const int*)  d_in[2];
    const int*   negs       = (const int*)  d_in[3];
    const float* W1         = (const float*)d_in[4];
    const float* a_src1     = (const float*)d_in[5];
    const float* a_dst1     = (const float*)d_in[6];
    const float* b1         = (const float*)d_in[7];
    const float* W2         = (const float*)d_in[8];
    const float* a_src2     = (const float*)d_in[9];
    const float* a_dst2     = (const float*)d_in[10];
    const float* b2         = (const float*)d_in[11];
    float* out = (float*)d_out;

    float *xw1, *emb1, *xw2, *emb2, *als1, *ald1, *als2, *ald2;
    cudaGetSymbolAddress((void**)&xw1,  g_xw1);
    cudaGetSymbolAddress((void**)&emb1, g_emb1);
    cudaGetSymbolAddress((void**)&xw2,  g_xw2);
    cudaGetSymbolAddress((void**)&emb2, g_emb2);
    cudaGetSymbolAddress((void**)&als1, g_als1);
    cudaGetSymbolAddress((void**)&ald1, g_ald1);
    cudaGetSymbolAddress((void**)&als2, g_als2);
    cudaGetSymbolAddress((void**)&ald2, g_ald2);

    // CSR build (shared by both layers)
    k_zero_deg<<<(NN + 255) / 256, 256>>>();
    k_count<<<(EE + 255) / 256, 256>>>(edge_index);
    k_scan<<<1, 1024>>>();
    k_scatter<<<(EE + 255) / 256, 256>>>(edge_index);

    // layer 1
    k_sgemm<<<dim3((NN + 127) / 128, 2), 256>>>(x, W1, xw1, NN, FIN);
    k_al<NHEADS, HID><<<(NN * NHEADS * 32 + 255) / 256, 256>>>(xw1, a_src1, a_dst1, als1, ald1);
    k_agg<NHEADS, true><<<NN, 256>>>(xw1, als1, ald1, b1, emb1);

    // layer 2
    k_sgemm<<<dim3((NN + 127) / 128, 2), 256>>>(emb1, W2, xw2, NN, H1);
    k_al<1, H1><<<(NN * 32 + 255) / 256, 256>>>(xw2, a_src2, a_dst2, als2, ald2);
    k_agg<1, false><<<NN, 256>>>(xw2, als2, ald2, b2, emb2);

    // loss
    k_norm<<<(NN * 32 + 255) / 256, 256>>>();
    k_loss<<<(NUM_WALKS * WALK_LEN * 32 + 255) / 256, 256>>>(walks, negs);
    k_reduce<<<1, 1024>>>(out);
}

// round 2
// speedup vs baseline: 1.2437x; 1.2437x over previous
#include <cuda_runtime.h>

#define NN 50000
#define EE 800000
#define FIN 128
#define HID 32
#define NHEADS 8
#define H1 256
#define NUM_WALKS 512
#define WALK_LEN 64
#define WINDOW 5
#define NEG_S 10
#define NEG_SLOPE 0.2f
#define INV_TEMP (1.0f/0.07f)

// ---------------- scratch (device globals; no cudaMalloc allowed) ----------
__device__ float g_xw1[(size_t)NN * H1];
__device__ float g_emb1[(size_t)NN * H1];
__device__ float g_xw2[(size_t)NN * H1];
__device__ float g_emb2[(size_t)NN * H1];
__device__ float g_als1[NN * NHEADS];
__device__ float g_ald1[NN * NHEADS];
__device__ float g_als2[NN];
__device__ float g_ald2[NN];
__device__ float g_ss1[NN];
__device__ float g_ss2[NN];
__device__ float g_inv[NN];
__device__ int   g_deg[NN];
__device__ int   g_rowptr[NN + 1];
__device__ int   g_wptr[NN];
__device__ int   g_col[EE];
__device__ float g_terms[NUM_WALKS];

// ---------------- CSR build ------------------------------------------------
__global__ void k_count(const int* __restrict__ edge_index) {
    int e = blockIdx.x * blockDim.x + threadIdx.x;
    if (e < EE) {
        int dst = edge_index[EE + e];
        atomicAdd(&g_deg[dst], 1);
    }
}

__global__ void k_scan() {   // single block, 1024 threads, shfl-based scan
    __shared__ int wsums[32];
    __shared__ int carry_s;
    int tid = threadIdx.x, lane = tid & 31, w = tid >> 5;
    if (tid == 0) carry_s = 0;
    __syncthreads();
    for (int base = 0; base < NN; base += 1024) {
        int i = base + tid;
        int v = (i < NN) ? g_deg[i] : 0;
        int inc = v;
#pragma unroll
        for (int o = 1; o < 32; o <<= 1) {
            int t = __shfl_up_sync(0xffffffffu, inc, o);
            if (lane >= o) inc += t;
        }
        if (lane == 31) wsums[w] = inc;
        __syncthreads();
        if (w == 0) {
            int ws = wsums[lane];
#pragma unroll
            for (int o = 1; o < 32; o <<= 1) {
                int t = __shfl_up_sync(0xffffffffu, ws, o);
                if (lane >= o) ws += t;
            }
            wsums[lane] = ws;
        }
        __syncthreads();
        int offset = carry_s + (w ? wsums[w - 1] : 0);
        int exc = offset + inc - v;
        if (i < NN) { g_rowptr[i] = exc; g_wptr[i] = exc; }
        __syncthreads();
        if (tid == 1023) carry_s = offset + inc;
        __syncthreads();
    }
    if (tid == 0) g_rowptr[NN] = carry_s;
}

__global__ void k_scatter(const int* __restrict__ edge_index) {
    int e = blockIdx.x * blockDim.x + threadIdx.x;
    if (e < EE) {
        int src = edge_index[e];
        int dst = edge_index[EE + e];
        int pos = atomicAdd(&g_wptr[dst], 1);
        g_col[pos] = src;
    }
}

// ---------------- SGEMM: C[M,256] = A[M,K] * B[K,256]  (fp32, FFMA2) -------
__global__ __launch_bounds__(256, 2)
void k_sgemm(const float* __restrict__ A, const float* __restrict__ B,
             float* __restrict__ C, int M, int K)
{
    __shared__ float As[8][128];
    __shared__ float Bs[8][128];
    const int N2 = 256;
    int tid = threadIdx.x;
    int tx = tid & 15, ty = tid >> 4;
    int rBase = blockIdx.x * 128;
    int cBase = blockIdx.y * 128;

    unsigned long long acc[4][8];
#pragma unroll
    for (int i = 0; i < 4; i++)
#pragma unroll
        for (int j = 0; j < 8; j++) acc[i][j] = 0ULL;

    int arow = tid >> 1;
    int acol = (tid & 1) * 4;
    int brow = tid >> 5;
    int bcol = (tid & 31) * 4;

    for (int k0 = 0; k0 < K; k0 += 8) {
        float4 av = make_float4(0.f, 0.f, 0.f, 0.f);
        int gr = rBase + arow;
        if (gr < M) av = *(const float4*)(A + (size_t)gr * K + k0 + acol);
        As[acol + 0][arow] = av.x;
        As[acol + 1][arow] = av.y;
        As[acol + 2][arow] = av.z;
        As[acol + 3][arow] = av.w;
        float4 bv = *(const float4*)(B + (size_t)(k0 + brow) * N2 + cBase + bcol);
        *(float4*)&Bs[brow][bcol] = bv;
        __syncthreads();
#pragma unroll
        for (int k = 0; k < 8; k++) {
            float4 a0 = *(float4*)&As[k][ty * 8];
            float4 a4 = *(float4*)&As[k][ty * 8 + 4];
            float4 b0 = *(float4*)&Bs[k][tx * 8];
            float4 b4 = *(float4*)&Bs[k][tx * 8 + 4];
            unsigned long long ar[4];
            asm("mov.b64 %0, {%1,%2};" : "=l"(ar[0]) : "r"(__float_as_uint(a0.x)), "r"(__float_as_uint(a0.y)));
            asm("mov.b64 %0, {%1,%2};" : "=l"(ar[1]) : "r"(__float_as_uint(a0.z)), "r"(__float_as_uint(a0.w)));
            asm("mov.b64 %0, {%1,%2};" : "=l"(ar[2]) : "r"(__float_as_uint(a4.x)), "r"(__float_as_uint(a4.y)));
            asm("mov.b64 %0, {%1,%2};" : "=l"(ar[3]) : "r"(__float_as_uint(a4.z)), "r"(__float_as_uint(a4.w)));
            float bs[8] = {b0.x, b0.y, b0.z, b0.w, b4.x, b4.y, b4.z, b4.w};
            unsigned long long bb[8];
#pragma unroll
            for (int j = 0; j < 8; j++) {
                unsigned r = __float_as_uint(bs[j]);
                asm("mov.b64 %0, {%1,%1};" : "=l"(bb[j]) : "r"(r));
            }
#pragma unroll
            for (int i = 0; i < 4; i++)
#pragma unroll
                for (int j = 0; j < 8; j++)
                    asm("fma.rn.f32x2 %0, %1, %2, %0;" : "+l"(acc[i][j]) : "l"(ar[i]), "l"(bb[j]));
        }
        __syncthreads();
    }
#pragma unroll
    for (int i = 0; i < 4; i++) {
        int r0 = rBase + ty * 8 + 2 * i;
#pragma unroll
        for (int j = 0; j < 8; j++) {
            int c = cBase + tx * 8 + j;
            float lo = __uint_as_float((unsigned)(acc[i][j] & 0xffffffffULL));
            float hi = __uint_as_float((unsigned)(acc[i][j] >> 32));
            if (r0 < M)     C[(size_t)r0 * N2 + c] = lo;
            if (r0 + 1 < M) C[(size_t)(r0 + 1) * N2 + c] = hi;
        }
    }
}

// ---------------- attention logits per node: al_s, al_d --------------------
template<int H, int C>
__global__ void k_al(const float* __restrict__ xw, const float* __restrict__ a_src,
                     const float* __restrict__ a_dst,
                     float* __restrict__ als, float* __restrict__ ald)
{
    int gw = (blockIdx.x * blockDim.x + threadIdx.x) >> 5;
    int lane = threadIdx.x & 31;
    if (gw >= NN * H) return;
    int n = gw / H, h = gw % H;
    const float* row = xw + (size_t)n * (H * C) + h * C;
    float s = 0.f, d = 0.f;
    for (int c = lane; c < C; c += 32) {
        float v = row[c];
        s += v * a_src[h * C + c];
        d += v * a_dst[h * C + c];
    }
#pragma unroll
    for (int o = 16; o; o >>= 1) {
        s += __shfl_down_sync(0xffffffffu, s, o);
        d += __shfl_down_sync(0xffffffffu, d, o);
    }
    if (lane == 0) { als[n * H + h] = s; ald[n * H + h] = d; }
}

// ---------------- warp-per-node softmax aggregation ------------------------
// out = (sum_j exp(e_j - m) * xw[src_j]) / den, fused single pass over nbrs.
template<int H, bool ELU>
__global__ __launch_bounds__(256)
void k_agg_w(const float* __restrict__ xw, const float* __restrict__ als,
             const float* __restrict__ ald, const float* __restrict__ bias,
             float* __restrict__ out, float* __restrict__ ssout)
{
    int gw = (blockIdx.x * blockDim.x + threadIdx.x) >> 5;
    int lane = threadIdx.x & 31;
    if (gw >= NN) return;
    int n = gw;
    int beg = g_rowptr[n];
    int deg = g_rowptr[n + 1] - beg;

    // per-head dst logits and self e (= max init)
    float adh[H], mx[H];
#pragma unroll
    for (int h = 0; h < H; h++) {
        adh[h] = ald[(size_t)n * H + h];
        float e = als[(size_t)n * H + h] + adh[h];
        mx[h] = e > 0.f ? e : NEG_SLOPE * e;
    }

    // pass 1: per-head max over neighbors
    for (int j = lane; j < deg; j += 32) {
        int s = g_col[beg + j];
        if (H == 8) {
            const float4* a4 = (const float4*)(als + (size_t)s * 8);
            float4 u0 = a4[0], u1 = a4[1];
            float ev[8] = {u0.x, u0.y, u0.z, u0.w, u1.x, u1.y, u1.z, u1.w};
#pragma unroll
            for (int h = 0; h < 8; h++) {
                float e = ev[h] + adh[h];
                e = e > 0.f ? e : NEG_SLOPE * e;
                mx[h] = fmaxf(mx[h], e);
            }
        } else {
            float e = als[s] + adh[0];
            e = e > 0.f ? e : NEG_SLOPE * e;
            mx[0] = fmaxf(mx[0], e);
        }
    }
#pragma unroll
    for (int h = 0; h < H; h++)
#pragma unroll
        for (int o = 16; o; o >>= 1)
            mx[h] = fmaxf(mx[h], __shfl_xor_sync(0xffffffffu, mx[h], o));

    // pass 2: fused den + weighted accumulate (lane owns 8 channels)
    const int myh = (lane * H) >> 5;          // H=8 -> lane/4, H=1 -> 0
    const float admy = adh[myh];
    const float mxmy = mx[myh];

    float eself = als[(size_t)n * H + myh] + admy;
    eself = eself > 0.f ? eself : NEG_SLOPE * eself;
    float exs = __expf(eself - mxmy);
    float den = exs;

    float acc[8];
    {
        const float4* xr = (const float4*)(xw + (size_t)n * 256 + (lane << 3));
        float4 v0 = xr[0], v1 = xr[1];
        acc[0] = exs * v0.x; acc[1] = exs * v0.y; acc[2] = exs * v0.z; acc[3] = exs * v0.w;
        acc[4] = exs * v1.x; acc[5] = exs * v1.y; acc[6] = exs * v1.z; acc[7] = exs * v1.w;
    }

    for (int base = 0; base < deg; base += 32) {
        int idx = base + lane;
        int scol = (idx < deg) ? g_col[beg + idx] : 0;
        int cn = min(32, deg - base);
#pragma unroll 4
        for (int jj = 0; jj < cn; jj++) {
            int s = __shfl_sync(0xffffffffu, scol, jj);
            float e = als[(size_t)s * H + myh] + admy;
            e = e > 0.f ? e : NEG_SLOPE * e;
            float ex = __expf(e - mxmy);
            den += ex;
            const float4* xr = (const float4*)(xw + (size_t)s * 256 + (lane << 3));
            float4 v0 = xr[0], v1 = xr[1];
            acc[0] += ex * v0.x; acc[1] += ex * v0.y; acc[2] += ex * v0.z; acc[3] += ex * v0.w;
            acc[4] += ex * v1.x; acc[5] += ex * v1.y; acc[6] += ex * v1.z; acc[7] += ex * v1.w;
        }
    }

    float invd = 1.f / den;
    const float4* bb = (const float4*)(bias + (lane << 3));
    float4 b0 = bb[0], b1 = bb[1];
    float o[8];
    o[0] = acc[0] * invd + b0.x; o[1] = acc[1] * invd + b0.y;
    o[2] = acc[2] * invd + b0.z; o[3] = acc[3] * invd + b0.w;
    o[4] = acc[4] * invd + b1.x; o[5] = acc[5] * invd + b1.y;
    o[6] = acc[6] * invd + b1.z; o[7] = acc[7] * invd + b1.w;
    float ssq = 0.f;
#pragma unroll
    for (int t = 0; t < 8; t++) {
        if (ELU) o[t] = o[t] > 0.f ? o[t] : expm1f(o[t]);
        ssq += o[t] * o[t];
    }
    float4* orow = (float4*)(out + (size_t)n * 256 + (lane << 3));
    orow[0] = make_float4(o[0], o[1], o[2], o[3]);
    orow[1] = make_float4(o[4], o[5], o[6], o[7]);
#pragma unroll
    for (int oo = 16; oo; oo >>= 1) ssq += __shfl_xor_sync(0xffffffffu, ssq, oo);
    if (lane == 0) ssout[n] = ssq;
}

// ---------------- inverse norms from partial sums --------------------------
__global__ void k_inv()
{
    int i = blockIdx.x * blockDim.x + threadIdx.x;
    if (i < NN) g_inv[i] = 1.f / fmaxf(sqrtf(g_ss1[i] + g_ss2[i]), 1e-8f);
}

// ---------------- contrastive loss: block per walk, smem-resident walk -----
// dim mapping: chunk c = q*32 + lane (q=0..3), each chunk = 1 float4.
// q=0,1 -> emb1 float4 idx {lane, 32+lane}; q=2,3 -> emb2 {lane, 32+lane}.
#define SMEM_EMB_F4 (WALK_LEN * 128)
#define SMEM_LOSS_BYTES (SMEM_EMB_F4 * 16 + WALK_LEN * 4 + WALK_LEN * 4 + 16 * 4)

__device__ __forceinline__ float dot16(const float4& a0, const float4& a1,
                                       const float4& a2, const float4& a3,
                                       const float4& p0, const float4& p1,
                                       const float4& p2, const float4& p3)
{
    float s = a0.x * p0.x + a0.y * p0.y + a0.z * p0.z + a0.w * p0.w
            + a1.x * p1.x + a1.y * p1.y + a1.z * p1.z + a1.w * p1.w
            + a2.x * p2.x + a2.y * p2.y + a2.z * p2.z + a2.w * p2.w
            + a3.x * p3.x + a3.y * p3.y + a3.z * p3.z + a3.w * p3.w;
#pragma unroll
    for (int o = 16; o; o >>= 1) s += __shfl_xor_sync(0xffffffffu, s, o);
    return s;
}

__global__ __launch_bounds__(512)
void k_loss(const int* __restrict__ walks, const int* __restrict__ negs)
{
    extern __shared__ char smraw[];
    float4* sm4   = (float4*)smraw;
    int*    ids_s = (int*)(smraw + SMEM_EMB_F4 * 16);
    float*  inv_s = (float*)(smraw + SMEM_EMB_F4 * 16 + WALK_LEN * 4);
    float*  wsum  = (float*)(smraw + SMEM_EMB_F4 * 16 + WALK_LEN * 8);

    int b = blockIdx.x;
    int tid = threadIdx.x, lane = tid & 31, w = tid >> 5;

    if (tid < WALK_LEN) {
        int id = walks[b * WALK_LEN + tid];
        ids_s[tid] = id;
        inv_s[tid] = g_inv[id];
    }
    __syncthreads();

    // load 64 rows x 512 floats (normalized) into smem
    const float4* e1 = (const float4*)g_emb1;
    const float4* e2 = (const float4*)g_emb2;
    for (int f = tid; f < SMEM_EMB_F4; f += 512) {
        int r = f >> 7, q = f & 127;
        int id = ids_s[r];
        float iv = inv_s[r];
        float4 v = (q < 64) ? e1[(size_t)id * 64 + q] : e2[(size_t)id * 64 + (q - 64)];
        v.x *= iv; v.y *= iv; v.z *= iv; v.w *= iv;
        sm4[f] = v;
    }
    __syncthreads();

    float term_acc = 0.f;
    // 16 warps x 4 anchors
    for (int k = 0; k < 4; k++) {
        int l = (w << 2) | k;
        const float4* ar = sm4 + (size_t)l * 128;
        float4 A0 = ar[lane], A1 = ar[32 + lane], A2 = ar[64 + lane], A3 = ar[96 + lane];

        int posid[2 * WINDOW];
        bool pval[2 * WINDOW];
        float pos_sum = 0.f;
#pragma unroll
        for (int p = 0; p < 2 * WINDOW; p++) {
            int off = (p < WINDOW) ? (p - WINDOW) : (p - WINDOW + 1);
            int pp = l + off;
            bool val = (pp >= 0) && (pp < WALK_LEN);
            int ppc = min(max(pp, 0), WALK_LEN - 1);
            pval[p] = val;
            posid[p] = ids_s[ppc];
            const float4* pr = sm4 + (size_t)ppc * 128;
            float4 P0 = pr[lane], P1 = pr[32 + lane], P2 = pr[64 + lane], P3 = pr[96 + lane];
            float d = dot16(A0, A1, A2, A3, P0, P1, P2, P3);
            if (val) pos_sum += __expf(d * INV_TEMP);
        }

        int nbase = (b * WALK_LEN + l) * NEG_S;
        int ngl = (lane < NEG_S) ? negs[nbase + lane] : 0;
        float neg_sum = 0.f;
#pragma unroll
        for (int s = 0; s < NEG_S; s++) {
            int ng = __shfl_sync(0xffffffffu, ngl, s);
            bool inpos = false;
#pragma unroll
            for (int p = 0; p < 2 * WINDOW; p++)
                inpos = inpos || (pval[p] && (ng == posid[p]));
            const float4* n1 = e1 + (size_t)ng * 64;
            const float4* n2 = e2 + (size_t)ng * 64;
            float4 P0 = n1[lane], P1 = n1[32 + lane], P2 = n2[lane], P3 = n2[32 + lane];
            float d = dot16(A0, A1, A2, A3, P0, P1, P2, P3);
            float sim = d * g_inv[ng] * INV_TEMP;
            if (!inpos) neg_sum += __expf(sim);
        }
        term_acc += log1pf(neg_sum / pos_sum);
    }

    if (lane == 0) wsum[w] = term_acc;
    __syncthreads();
    if (w == 0) {
        float s = (lane < 16) ? wsum[lane] : 0.f;
#pragma unroll
        for (int o = 16; o; o >>= 1) s += __shfl_xor_sync(0xffffffffu, s, o);
        if (lane == 0) g_terms[b] = s;
    }
}

__global__ void k_reduce(float* __restrict__ out)
{
    __shared__ float sh[512];
    int tid = threadIdx.x;
    float s = (tid < NUM_WALKS) ? g_terms[tid] : 0.f;
    sh[tid] = s;
    __syncthreads();
    for (int o = 256; o; o >>= 1) {
        if (tid < o) sh[tid] += sh[tid + o];
        __syncthreads();
    }
    if (tid == 0) out[0] = sh[0];
}

// ---------------- driver ---------------------------------------------------
extern "C" void kernel_launch(void* const* d_in, const int* in_sizes, int n_in,
                              void* d_out, int out_size)
{
    const float* x          = (const float*)d_in[0];
    const int*   edge_index = (const int*)  d_in[1];
    const int*   walks      = (const int*)  d_in[2];
    const int*   negs       = (const int*)  d_in[3];
    const float* W1         = (const float*)d_in[4];
    const float* a_src1     = (const float*)d_in[5];
    const float* a_dst1     = (const float*)d_in[6];
    const float* b1         = (const float*)d_in[7];
    const float* W2         = (const float*)d_in[8];
    const float* a_src2     = (const float*)d_in[9];
    const float* a_dst2     = (const float*)d_in[10];
    const float* b2         = (const float*)d_in[11];
    float* out = (float*)d_out;

    float *xw1, *emb1, *xw2, *emb2, *als1, *ald1, *als2, *ald2, *ss1, *ss2;
    void* degp;
    cudaGetSymbolAddress((void**)&xw1,  g_xw1);
    cudaGetSymbolAddress((void**)&emb1, g_emb1);
    cudaGetSymbolAddress((void**)&xw2,  g_xw2);
    cudaGetSymbolAddress((void**)&emb2, g_emb2);
    cudaGetSymbolAddress((void**)&als1, g_als1);
    cudaGetSymbolAddress((void**)&ald1, g_ald1);
    cudaGetSymbolAddress((void**)&als2, g_als2);
    cudaGetSymbolAddress((void**)&ald2, g_ald2);
    cudaGetSymbolAddress((void**)&ss1,  g_ss1);
    cudaGetSymbolAddress((void**)&ss2,  g_ss2);
    cudaGetSymbolAddress(&degp, g_deg);

    static int smem_set = 0;
    if (!smem_set) {
        cudaFuncSetAttribute(k_loss, cudaFuncAttributeMaxDynamicSharedMemorySize,
                             SMEM_LOSS_BYTES);
        smem_set = 1;
    }

    // CSR build
    cudaMemsetAsync(degp, 0, NN * sizeof(int));
    k_count<<<(EE + 255) / 256, 256>>>(edge_index);
    k_scan<<<1, 1024>>>();
    k_scatter<<<(EE + 255) / 256, 256>>>(edge_index);

    // layer 1
    k_sgemm<<<dim3((NN + 127) / 128, 2), 256>>>(x, W1, xw1, NN, FIN);
    k_al<NHEADS, HID><<<(NN * NHEADS * 32 + 255) / 256, 256>>>(xw1, a_src1, a_dst1, als1, ald1);
    k_agg_w<NHEADS, true><<<(NN * 32 + 255) / 256, 256>>>(xw1, als1, ald1, b1, emb1, ss1);

    // layer 2
    k_sgemm<<<dim3((NN + 127) / 128, 2), 256>>>(emb1, W2, xw2, NN, H1);
    k_al<1, H1><<<(NN * 32 + 255) / 256, 256>>>(xw2, a_src2, a_dst2, als2, ald2);
    k_agg_w<1, false><<<(NN * 32 + 255) / 256, 256>>>(xw2, als2, ald2, b2, emb2, ss2);

    // loss
    k_inv<<<(NN + 255) / 256, 256>>>();
    k_loss<<<NUM_WALKS, 512, SMEM_LOSS_BYTES>>>(walks, negs);
    k_reduce<<<1, 512>>>(out);
}

// round 4
// speedup vs baseline: 1.7973x; 1.4451x over previous
#include <cuda_runtime.h>
#include <cuda_bf16.h>
#include <cstdint>

#define NN 50000
#define NPAD 50048
#define EE 800000
#define FIN 128
#define HID 32
#define NHEADS 8
#define H1 256
#define NUM_WALKS 512
#define WALK_LEN 64
#define WINDOW 5
#define NEG_S 10
#define NEG_SLOPE 0.2f
#define INV_TEMP (1.0f/0.07f)

// ---------------- scratch (device globals; no cudaMalloc allowed) ----------
__device__ float g_xw1[(size_t)NPAD * H1];
__device__ float g_emb1[(size_t)NN * H1];
__device__ float g_xw2[(size_t)NPAD * H1];
__device__ float g_emb2[(size_t)NN * H1];
__device__ float g_als1[NN * NHEADS];
__device__ float g_ald1[NN * NHEADS];
__device__ float g_als2[NN];
__device__ float g_ald2[NN];
__device__ float g_ss1[NN];
__device__ float g_ss2[NN];
__device__ float g_inv[NN];
__device__ int   g_deg[NN];
__device__ int   g_rowptr[NN + 1];
__device__ int   g_wptr[NN];
__device__ int   g_col[EE];
__device__ float g_terms[NUM_WALKS];
// bf16 split operands (device globals are zero-init; pad rows stay zero)
__device__ __nv_bfloat16 g_a1h[(size_t)NPAD * FIN];
__device__ __nv_bfloat16 g_a1l[(size_t)NPAD * FIN];
__device__ __nv_bfloat16 g_a2h[(size_t)NPAD * H1];
__device__ __nv_bfloat16 g_a2l[(size_t)NPAD * H1];
__device__ __nv_bfloat16 g_b1h[256 * FIN];   // Wt1 [N=256][K=128]
__device__ __nv_bfloat16 g_b1l[256 * FIN];
__device__ __nv_bfloat16 g_b2h[256 * H1];    // Wt2 [N=256][K=256]
__device__ __nv_bfloat16 g_b2l[256 * H1];

// ---------------- PTX helpers (arch-generic: sm_80+ instructions only) -----
__device__ __forceinline__ uint32_t smem_u32(const void* p) {
    uint32_t a;
    asm("{ .reg .u64 t; cvta.to.shared.u64 t, %1; cvt.u32.u64 %0, t; }" : "=r"(a) : "l"(p));
    return a;
}
#define CP16(SADDR, GPTR) \
    asm volatile("cp.async.cg.shared.global [%0], [%1], 16;" :: "r"(SADDR), "l"(GPTR))
#define CP_COMMIT() asm volatile("cp.async.commit_group;" ::: "memory")
#define CP_WAIT(N)  asm volatile("cp.async.wait_group %0;" :: "n"(N) : "memory")
#define LDSM4(R, ADDR) \
    asm volatile("ldmatrix.sync.aligned.m8n8.x4.shared.b16 {%0,%1,%2,%3}, [%4];" \
        : "=r"((R)[0]), "=r"((R)[1]), "=r"((R)[2]), "=r"((R)[3]) : "r"(ADDR))
#define MMA16816(C, A, B0, B1) \
    asm volatile("mma.sync.aligned.m16n8k16.row.col.f32.bf16.bf16.f32 " \
        "{%0,%1,%2,%3}, {%4,%5,%6,%7}, {%8,%9}, {%0,%1,%2,%3};" \
        : "+f"((C)[0]), "+f"((C)[1]), "+f"((C)[2]), "+f"((C)[3]) \
        : "r"((A)[0]), "r"((A)[1]), "r"((A)[2]), "r"((A)[3]), "r"(B0), "r"(B1))

__device__ __forceinline__ unsigned pk_bf2(float a, float b) {
    __nv_bfloat162 t;
    t.x = __float2bfloat16_rn(a);
    t.y = __float2bfloat16_rn(b);
    return *reinterpret_cast<unsigned*>(&t);
}

// ---------------- CSR build ------------------------------------------------
__global__ void k_count(const int* __restrict__ edge_index) {
    int e = blockIdx.x * blockDim.x + threadIdx.x;
    if (e < EE) atomicAdd(&g_deg[edge_index[EE + e]], 1);
}

__global__ void k_scan() {
    __shared__ int wsums[32];
    __shared__ int carry_s;
    int tid = threadIdx.x, lane = tid & 31, w = tid >> 5;
    if (tid == 0) carry_s = 0;
    __syncthreads();
    for (int base = 0; base < NN; base += 1024) {
        int i = base + tid;
        int v = (i < NN) ? g_deg[i] : 0;
        int inc = v;
#pragma unroll
        for (int o = 1; o < 32; o <<= 1) {
            int t = __shfl_up_sync(0xffffffffu, inc, o);
            if (lane >= o) inc += t;
        }
        if (lane == 31) wsums[w] = inc;
        __syncthreads();
        if (w == 0) {
            int ws = wsums[lane];
#pragma unroll
            for (int o = 1; o < 32; o <<= 1) {
                int t = __shfl_up_sync(0xffffffffu, ws, o);
                if (lane >= o) ws += t;
            }
            wsums[lane] = ws;
        }
        __syncthreads();
        int offset = carry_s + (w ? wsums[w - 1] : 0);
        int exc = offset + inc - v;
        if (i < NN) { g_rowptr[i] = exc; g_wptr[i] = exc; }
        __syncthreads();
        if (tid == 1023) carry_s = offset + inc;
        __syncthreads();
    }
    if (tid == 0) g_rowptr[NN] = carry_s;
}

__global__ void k_scatter(const int* __restrict__ edge_index) {
    int e = blockIdx.x * blockDim.x + threadIdx.x;
    if (e < EE) {
        int src = edge_index[e];
        int dst = edge_index[EE + e];
        g_col[atomicAdd(&g_wptr[dst], 1)] = src;
    }
}

// ---------------- bf16 split conversions -----------------------------------
__global__ void k_split_x(const float* __restrict__ x) {
    int t = blockIdx.x * blockDim.x + threadIdx.x;
    if (t >= NPAD * FIN / 4) return;
    int base = t * 4;
    int row = base >> 7;
    float4 v = (row < NN) ? *(const float4*)(x + base) : make_float4(0.f, 0.f, 0.f, 0.f);
    float a[4] = {v.x, v.y, v.z, v.w};
    float l[4];
#pragma unroll
    for (int i = 0; i < 4; i++)
        l[i] = a[i] - __bfloat162float(__float2bfloat16_rn(a[i]));
    *(uint2*)(g_a1h + base) = make_uint2(pk_bf2(a[0], a[1]), pk_bf2(a[2], a[3]));
    *(uint2*)(g_a1l + base) = make_uint2(pk_bf2(l[0], l[1]), pk_bf2(l[2], l[3]));
}

__global__ void k_split_w(const float* __restrict__ W, __nv_bfloat16* __restrict__ h,
                          __nv_bfloat16* __restrict__ l, int K) {
    int t = blockIdx.x * blockDim.x + threadIdx.x;
    if (t >= 256 * K) return;
    int n = t / K, k = t - n * K;
    float v = W[k * 256 + n];
    __nv_bfloat16 hb = __float2bfloat16_rn(v);
    h[t] = hb;
    l[t] = __float2bfloat16_rn(v - __bfloat162float(hb));
}

// ---------------- HMMA split-bf16 GEMM: C[NPAD,256] = A[NPAD,K]*B[K,256] ----
// CTA tile 128(M) x 128(N), 8 warps (64x32), K-chunk 32, 2-stage cp.async.
// smem per stage: Ah|Al|Bh|Bl, each 128 rows x (32+8) bf16 (80B stride).
#define MBUF 10240
#define MSTAGE (4 * MBUF)
#define MSM_TOTAL (2 * MSTAGE)

__device__ __forceinline__ void stage_chunk(
    uint32_t sb32, int rbase, int nbase, int k0, int K, int tid,
    const __nv_bfloat16* __restrict__ Ah, const __nv_bfloat16* __restrict__ Al,
    const __nv_bfloat16* __restrict__ Bh, const __nv_bfloat16* __restrict__ Bl)
{
#pragma unroll
    for (int t = tid; t < 512; t += 256) {
        int r = t >> 2, seg = t & 3;
        uint32_t so = sb32 + r * 80 + seg * 16;
        size_t ga = (size_t)(rbase + r) * K + k0 + seg * 8;
        size_t gb = (size_t)(nbase + r) * K + k0 + seg * 8;
        CP16(so,             Ah + ga);
        CP16(so + MBUF,      Al + ga);
        CP16(so + 2 * MBUF,  Bh + gb);
        CP16(so + 3 * MBUF,  Bl + gb);
    }
}

__global__ __launch_bounds__(256)
void k_mmagemm(const __nv_bfloat16* __restrict__ Ah, const __nv_bfloat16* __restrict__ Al,
               const __nv_bfloat16* __restrict__ Bh, const __nv_bfloat16* __restrict__ Bl,
               float* __restrict__ C, int K)
{
    extern __shared__ char sm[];
    uint32_t smb = smem_u32(sm);
    int tid = threadIdx.x, lane = tid & 31, wid = tid >> 5;
    int rbase = blockIdx.x * 128, nbase = blockIdx.y * 128;
    int wm = (wid >> 2) * 64, wn = (wid & 3) * 32;

    float acc[4][4][4];
#pragma unroll
    for (int i = 0; i < 4; i++)
#pragma unroll
        for (int j = 0; j < 4; j++)
#pragma unroll
            for (int q = 0; q < 4; q++) acc[i][j][q] = 0.f;

    int nch = K >> 5;
    stage_chunk(smb, rbase, nbase, 0, K, tid, Ah, Al, Bh, Bl);
    CP_COMMIT();

    int row = lane & 15, kh = lane >> 4;
    for (int ch = 0; ch < nch; ch++) {
        if (ch + 1 < nch) {
            stage_chunk(smb + ((ch + 1) & 1) * MSTAGE, rbase, nbase, (ch + 1) << 5, K, tid,
                        Ah, Al, Bh, Bl);
            CP_COMMIT();
            CP_WAIT(1);
        } else {
            CP_WAIT(0);
        }
        __syncthreads();

        uint32_t s0 = smb + (ch & 1) * MSTAGE;
#pragma unroll
        for (int s = 0; s < 2; s++) {
            int colb = (s * 16 + kh * 8) * 2;
            uint32_t ah[4][4], al[4][4], bh[2][4], bl[2][4];
#pragma unroll
            for (int mi = 0; mi < 4; mi++) {
                uint32_t ad = s0 + (wm + mi * 16 + row) * 80 + colb;
                LDSM4(ah[mi], ad);
                LDSM4(al[mi], ad + MBUF);
            }
#pragma unroll
            for (int bi = 0; bi < 2; bi++) {
                uint32_t ad = s0 + 2 * MBUF + (wn + bi * 16 + row) * 80 + colb;
                LDSM4(bh[bi], ad);
                LDSM4(bl[bi], ad + MBUF);
            }
#pragma unroll
            for (int mi = 0; mi < 4; mi++)
#pragma unroll
                for (int ni = 0; ni < 4; ni++) {
                    int bi = ni >> 1, hf = ni & 1;
                    MMA16816(acc[mi][ni], ah[mi], bh[bi][hf], bh[bi][hf + 2]);
                    MMA16816(acc[mi][ni], ah[mi], bl[bi][hf], bl[bi][hf + 2]);
                    MMA16816(acc[mi][ni], al[mi], bh[bi][hf], bh[bi][hf + 2]);
                }
        }
        __syncthreads();
    }

#pragma unroll
    for (int mi = 0; mi < 4; mi++)
#pragma unroll
        for (int ni = 0; ni < 4; ni++) {
            int r0 = rbase + wm + mi * 16 + (lane >> 2);
            int c  = nbase + wn + ni * 8 + (lane & 3) * 2;
            float* p = C + (size_t)r0 * 256 + c;
            *(float2*)p = make_float2(acc[mi][ni][0], acc[mi][ni][1]);
            *(float2*)(p + 8 * 256) = make_float2(acc[mi][ni][2], acc[mi][ni][3]);
        }
}

// ---------------- attention logits per node --------------------------------
template<int H, int C>
__global__ void k_al(const float* __restrict__ xw, const float* __restrict__ a_src,
                     const float* __restrict__ a_dst,
                     float* __restrict__ als, float* __restrict__ ald)
{
    int gw = (blockIdx.x * blockDim.x + threadIdx.x) >> 5;
    int lane = threadIdx.x & 31;
    if (gw >= NN * H) return;
    int n = gw / H, h = gw % H;
    const float* row = xw + (size_t)n * (H * C) + h * C;
    float s = 0.f, d = 0.f;
    for (int c = lane; c < C; c += 32) {
        float v = row[c];
        s += v * a_src[h * C + c];
        d += v * a_dst[h * C + c];
    }
#pragma unroll
    for (int o = 16; o; o >>= 1) {
        s += __shfl_down_sync(0xffffffffu, s, o);
        d += __shfl_down_sync(0xffffffffu, d, o);
    }
    if (lane == 0) { als[n * H + h] = s; ald[n * H + h] = d; }
}

// ---------------- warp-per-node softmax aggregation (no max pass) ----------
template<int H, bool ELU, bool SPLIT>
__global__ __launch_bounds__(256)
void k_agg_w(const float* __restrict__ xw, const float* __restrict__ als,
             const float* __restrict__ ald, const float* __restrict__ bias,
             float* __restrict__ out, float* __restrict__ ssout,
             __nv_bfloat16* __restrict__ sph, __nv_bfloat16* __restrict__ spl)
{
    int gw = (blockIdx.x * blockDim.x + threadIdx.x) >> 5;
    int lane = threadIdx.x & 31;
    if (gw >= NN) return;
    int n = gw;
    int beg = g_rowptr[n];
    int deg = g_rowptr[n + 1] - beg;

    const int myh = (lane * H) >> 5;
    const float admy = ald[(size_t)n * H + myh];

    float eself = als[(size_t)n * H + myh] + admy;
    eself = eself > 0.f ? eself : NEG_SLOPE * eself;
    float exs = __expf(eself);
    float den = exs;

    float acc[8];
    {
        const float4* xr = (const float4*)(xw + (size_t)n * 256 + (lane << 3));
        float4 v0 = xr[0], v1 = xr[1];
        acc[0] = exs * v0.x; acc[1] = exs * v0.y; acc[2] = exs * v0.z; acc[3] = exs * v0.w;
        acc[4] = exs * v1.x; acc[5] = exs * v1.y; acc[6] = exs * v1.z; acc[7] = exs * v1.w;
    }

    for (int base = 0; base < deg; base += 32) {
        int idx = base + lane;
        int scol = (idx < deg) ? g_col[beg + idx] : 0;
        int cn = min(32, deg - base);
#pragma unroll 4
        for (int jj = 0; jj < cn; jj++) {
            int s = __shfl_sync(0xffffffffu, scol, jj);
            float e = als[(size_t)s * H + myh] + admy;
            e = e > 0.f ? e : NEG_SLOPE * e;
            float ex = __expf(e);
            den += ex;
            const float4* xr = (const float4*)(xw + (size_t)s * 256 + (lane << 3));
            float4 v0 = xr[0], v1 = xr[1];
            acc[0] += ex * v0.x; acc[1] += ex * v0.y; acc[2] += ex * v0.z; acc[3] += ex * v0.w;
            acc[4] += ex * v1.x; acc[5] += ex * v1.y; acc[6] += ex * v1.z; acc[7] += ex * v1.w;
        }
    }

    float invd = 1.f / den;
    const float4* bb = (const float4*)(bias + (lane << 3));
    float4 b0 = bb[0], b1 = bb[1];
    float o[8];
    o[0] = acc[0] * invd + b0.x; o[1] = acc[1] * invd + b0.y;
    o[2] = acc[2] * invd + b0.z; o[3] = acc[3] * invd + b0.w;
    o[4] = acc[4] * invd + b1.x; o[5] = acc[5] * invd + b1.y;
    o[6] = acc[6] * invd + b1.z; o[7] = acc[7] * invd + b1.w;
    float ssq = 0.f;
#pragma unroll
    for (int t = 0; t < 8; t++) {
        if (ELU) o[t] = o[t] > 0.f ? o[t] : expm1f(o[t]);
        ssq += o[t] * o[t];
    }
    float4* orow = (float4*)(out + (size_t)n * 256 + (lane << 3));
    orow[0] = make_float4(o[0], o[1], o[2], o[3]);
    orow[1] = make_float4(o[4], o[5], o[6], o[7]);
    if (SPLIT) {
        unsigned hh[4], ll[4];
#pragma unroll
        for (int t2 = 0; t2 < 4; t2++) {
            float a = o[2 * t2], b = o[2 * t2 + 1];
            float la = a - __bfloat162float(__float2bfloat16_rn(a));
            float lb = b - __bfloat162float(__float2bfloat16_rn(b));
            hh[t2] = pk_bf2(a, b);
            ll[t2] = pk_bf2(la, lb);
        }
        *(uint4*)(sph + (size_t)n * 256 + (lane << 3)) = make_uint4(hh[0], hh[1], hh[2], hh[3]);
        *(uint4*)(spl + (size_t)n * 256 + (lane << 3)) = make_uint4(ll[0], ll[1], ll[2], ll[3]);
    }
#pragma unroll
    for (int oo = 16; oo; oo >>= 1) ssq += __shfl_xor_sync(0xffffffffu, ssq, oo);
    if (lane == 0) ssout[n] = ssq;
}

// ---------------- inverse norms --------------------------------------------
__global__ void k_inv()
{
    int i = blockIdx.x * blockDim.x + threadIdx.x;
    if (i < NN) g_inv[i] = 1.f / fmaxf(sqrtf(g_ss1[i] + g_ss2[i]), 1e-8f);
}

// ---------------- contrastive loss: block per walk -------------------------
#define SMEM_EMB_F4 (WALK_LEN * 128)
#define SMEM_LOSS_BYTES (SMEM_EMB_F4 * 16 + WALK_LEN * 4 + WALK_LEN * 4 + 16 * 4)

__device__ __forceinline__ float dot16(const float4& a0, const float4& a1,
                                       const float4& a2, const float4& a3,
                                       const float4& p0, const float4& p1,
                                       const float4& p2, const float4& p3)
{
    float s = a0.x * p0.x + a0.y * p0.y + a0.z * p0.z + a0.w * p0.w
            + a1.x * p1.x + a1.y * p1.y + a1.z * p1.z + a1.w * p1.w
            + a2.x * p2.x + a2.y * p2.y + a2.z * p2.z + a2.w * p2.w
            + a3.x * p3.x + a3.y * p3.y + a3.z * p3.z + a3.w * p3.w;
#pragma unroll
    for (int o = 16; o; o >>= 1) s += __shfl_xor_sync(0xffffffffu, s, o);
    return s;
}

__global__ __launch_bounds__(512)
void k_loss(const int* __restrict__ walks, const int* __restrict__ negs)
{
    extern __shared__ char smraw[];
    float4* sm4   = (float4*)smraw;
    int*    ids_s = (int*)(smraw + SMEM_EMB_F4 * 16);
    float*  inv_s = (float*)(smraw + SMEM_EMB_F4 * 16 + WALK_LEN * 4);
    float*  wsum  = (float*)(smraw + SMEM_EMB_F4 * 16 + WALK_LEN * 8);

    int b = blockIdx.x;
    int tid = threadIdx.x, lane = tid & 31, w = tid >> 5;

    if (tid < WALK_LEN) {
        int id = walks[b * WALK_LEN + tid];
        ids_s[tid] = id;
        inv_s[tid] = g_inv[id];
    }
    __syncthreads();

    const float4* e1 = (const float4*)g_emb1;
    const float4* e2 = (const float4*)g_emb2;
    for (int f = tid; f < SMEM_EMB_F4; f += 512) {
        int r = f >> 7, q = f & 127;
        int id = ids_s[r];
        float iv = inv_s[r];
        float4 v = (q < 64) ? e1[(size_t)id * 64 + q] : e2[(size_t)id * 64 + (q - 64)];
        v.x *= iv; v.y *= iv; v.z *= iv; v.w *= iv;
        sm4[f] = v;
    }
    __syncthreads();

    float term_acc = 0.f;
    for (int k = 0; k < 4; k++) {
        int l = (w << 2) | k;
        const float4* ar = sm4 + (size_t)l * 128;
        float4 A0 = ar[lane], A1 = ar[32 + lane], A2 = ar[64 + lane], A3 = ar[96 + lane];

        int posid[2 * WINDOW];
        bool pval[2 * WINDOW];
        float pos_sum = 0.f;
#pragma unroll
        for (int p = 0; p < 2 * WINDOW; p++) {
            int off = (p < WINDOW) ? (p - WINDOW) : (p - WINDOW + 1);
            int pp = l + off;
            bool val = (pp >= 0) && (pp < WALK_LEN);
            int ppc = min(max(pp, 0), WALK_LEN - 1);
            pval[p] = val;
            posid[p] = ids_s[ppc];
            const float4* pr = sm4 + (size_t)ppc * 128;
            float4 P0 = pr[lane], P1 = pr[32 + lane], P2 = pr[64 + lane], P3 = pr[96 + lane];
            float d = dot16(A0, A1, A2, A3, P0, P1, P2, P3);
            if (val) pos_sum += __expf(d * INV_TEMP);
        }

        int nbase = (b * WALK_LEN + l) * NEG_S;
        int ngl = (lane < NEG_S) ? negs[nbase + lane] : 0;
        float neg_sum = 0.f;
#pragma unroll
        for (int s = 0; s < NEG_S; s++) {
            int ng = __shfl_sync(0xffffffffu, ngl, s);
            bool inpos = false;
#pragma unroll
            for (int p = 0; p < 2 * WINDOW; p++)
                inpos = inpos || (pval[p] && (ng == posid[p]));
            const float4* n1 = e1 + (size_t)ng * 64;
            const float4* n2 = e2 + (size_t)ng * 64;
            float4 P0 = n1[lane], P1 = n1[32 + lane], P2 = n2[lane], P3 = n2[32 + lane];
            float d = dot16(A0, A1, A2, A3, P0, P1, P2, P3);
            float sim = d * g_inv[ng] * INV_TEMP;
            if (!inpos) neg_sum += __expf(sim);
        }
        term_acc += log1pf(neg_sum / pos_sum);
    }

    if (lane == 0) wsum[w] = term_acc;
    __syncthreads();
    if (w == 0) {
        float s = (lane < 16) ? wsum[lane] : 0.f;
#pragma unroll
        for (int o = 16; o; o >>= 1) s += __shfl_xor_sync(0xffffffffu, s, o);
        if (lane == 0) g_terms[b] = s;
    }
}

__global__ void k_reduce(float* __restrict__ out)
{
    __shared__ float sh[512];
    int tid = threadIdx.x;
    sh[tid] = (tid < NUM_WALKS) ? g_terms[tid] : 0.f;
    __syncthreads();
    for (int o = 256; o; o >>= 1) {
        if (tid < o) sh[tid] += sh[tid + o];
        __syncthreads();
    }
    if (tid == 0) out[0] = sh[0];
}

// ---------------- driver ---------------------------------------------------
extern "C" void kernel_launch(void* const* d_in, const int* in_sizes, int n_in,
                              void* d_out, int out_size)
{
    const float* x          = (const float*)d_in[0];
    const int*   edge_index = (const int*)  d_in[1];
    const int*   walks      = (const int*)  d_in[2];
    const int*   negs       = (const int*)  d_in[3];
    const float* W1         = (const float*)d_in[4];
    const float* a_src1     = (const float*)d_in[5];
    const float* a_dst1     = (const float*)d_in[6];
    const float* b1         = (const float*)d_in[7];
    const float* W2         = (const float*)d_in[8];
    const float* a_src2     = (const float*)d_in[9];
    const float* a_dst2     = (const float*)d_in[10];
    const float* b2         = (const float*)d_in[11];
    float* out = (float*)d_out;

    float *xw1, *emb1, *xw2, *emb2, *als1, *ald1, *als2, *ald2, *ss1, *ss2;
    __nv_bfloat16 *a1h, *a1l, *a2h, *a2l, *bw1h, *bw1l, *bw2h, *bw2l;
    void* degp;
    cudaGetSymbolAddress((void**)&xw1,  g_xw1);
    cudaGetSymbolAddress((void**)&emb1, g_emb1);
    cudaGetSymbolAddress((void**)&xw2,  g_xw2);
    cudaGetSymbolAddress((void**)&emb2, g_emb2);
    cudaGetSymbolAddress((void**)&als1, g_als1);
    cudaGetSymbolAddress((void**)&ald1, g_ald1);
    cudaGetSymbolAddress((void**)&als2, g_als2);
    cudaGetSymbolAddress((void**)&ald2, g_ald2);
    cudaGetSymbolAddress((void**)&ss1,  g_ss1);
    cudaGetSymbolAddress((void**)&ss2,  g_ss2);
    cudaGetSymbolAddress((void**)&a1h,  g_a1h);
    cudaGetSymbolAddress((void**)&a1l,  g_a1l);
    cudaGetSymbolAddress((void**)&a2h,  g_a2h);
    cudaGetSymbolAddress((void**)&a2l,  g_a2l);
    cudaGetSymbolAddress((void**)&bw1h, g_b1h);
    cudaGetSymbolAddress((void**)&bw1l, g_b1l);
    cudaGetSymbolAddress((void**)&bw2h, g_b2h);
    cudaGetSymbolAddress((void**)&bw2l, g_b2l);
    cudaGetSymbolAddress(&degp, g_deg);

    static int attr_set = 0;
    if (!attr_set) {
        cudaFuncSetAttribute(k_loss, cudaFuncAttributeMaxDynamicSharedMemorySize,
                             SMEM_LOSS_BYTES);
        cudaFuncSetAttribute(k_mmagemm, cudaFuncAttributeMaxDynamicSharedMemorySize,
                             MSM_TOTAL);
        attr_set = 1;
    }

    // CSR build
    cudaMemsetAsync(degp, 0, NN * sizeof(int));
    k_count<<<(EE + 255) / 256, 256>>>(edge_index);
    k_scan<<<1, 1024>>>();
    k_scatter<<<(EE + 255) / 256, 256>>>(edge_index);

    // operand conversions
    k_split_x<<<(NPAD * FIN / 4 + 255) / 256, 256>>>(x);
    k_split_w<<<(256 * FIN + 255) / 256, 256>>>(W1, bw1h, bw1l, FIN);
    k_split_w<<<(256 * H1 + 255) / 256, 256>>>(W2, bw2h, bw2l, H1);

    // layer 1
    k_mmagemm<<<dim3(NPAD / 128, 2), 256, MSM_TOTAL>>>(a1h, a1l, bw1h, bw1l, xw1, FIN);
    k_al<NHEADS, HID><<<(NN * NHEADS * 32 + 255) / 256, 256>>>(xw1, a_src1, a_dst1, als1, ald1);
    k_agg_w<NHEADS, true, true><<<(NN * 32 + 255) / 256, 256>>>(xw1, als1, ald1, b1, emb1, ss1, a2h, a2l);

    // layer 2
    k_mmagemm<<<dim3(NPAD / 128, 2), 256, MSM_TOTAL>>>(a2h, a2l, bw2h, bw2l, xw2, H1);
    k_al<1, H1><<<(NN * 32 + 255) / 256, 256>>>(xw2, a_src2, a_dst2, als2, ald2);
    k_agg_w<1, false, false><<<(NN * 32 + 255) / 256, 256>>>(xw2, als2, ald2, b2, emb2, ss2, nullptr, nullptr);

    // loss
    k_inv<<<(NN + 255) / 256, 256>>>();
    k_loss<<<NUM_WALKS, 512, SMEM_LOSS_BYTES>>>(walks, negs);
    k_reduce<<<1, 512>>>(out);
}

// round 5
// speedup vs baseline: 2.1618x; 1.2028x over previous
#include <cuda_runtime.h>
#include <cuda_bf16.h>
#include <cuda_fp16.h>
#include <cstdint>

#define NN 50000
#define NPAD 50048
#define EE 800000
#define FIN 128
#define HID 32
#define NHEADS 8
#define H1 256
#define NUM_WALKS 512
#define WALK_LEN 64
#define WINDOW 5
#define NEG_S 10
#define NEG_SLOPE 0.2f
#define INV_TEMP (1.0f/0.07f)

// ---------------- scratch (device globals; no cudaMalloc allowed) ----------
__device__ __half g_xw1h[(size_t)NPAD * H1];   // fp16 xw (gather + al)
__device__ __half g_xw2h[(size_t)NPAD * H1];
__device__ __half g_e1h[(size_t)NN * H1];      // fp16 emb (loss gathers)
__device__ __half g_e2h[(size_t)NN * H1];
__device__ float g_als1[NN * NHEADS];
__device__ float g_ald1[NN * NHEADS];
__device__ float g_als2[NN];
__device__ float g_ald2[NN];
__device__ float g_ss1[NN];
__device__ float g_ss2[NN];
__device__ float g_inv[NN];
__device__ int   g_deg[NN];
__device__ int   g_rowptr[NN + 1];
__device__ int   g_wptr[NN];
__device__ int   g_col[EE];
__device__ float g_terms[NUM_WALKS];
// bf16 split operands (zero-init; pad rows stay zero)
__device__ __nv_bfloat16 g_a1h[(size_t)NPAD * FIN];
__device__ __nv_bfloat16 g_a1l[(size_t)NPAD * FIN];
__device__ __nv_bfloat16 g_a2h[(size_t)NPAD * H1];
__device__ __nv_bfloat16 g_a2l[(size_t)NPAD * H1];
__device__ __nv_bfloat16 g_b1h[256 * FIN];
__device__ __nv_bfloat16 g_b1l[256 * FIN];
__device__ __nv_bfloat16 g_b2h[256 * H1];
__device__ __nv_bfloat16 g_b2l[256 * H1];

// ---------------- PTX helpers (arch-generic sm_80+) ------------------------
__device__ __forceinline__ uint32_t smem_u32(const void* p) {
    uint32_t a;
    asm("{ .reg .u64 t; cvta.to.shared.u64 t, %1; cvt.u32.u64 %0, t; }" : "=r"(a) : "l"(p));
    return a;
}
#define CP16(SADDR, GPTR) \
    asm volatile("cp.async.cg.shared.global [%0], [%1], 16;" :: "r"(SADDR), "l"(GPTR))
#define CP_COMMIT() asm volatile("cp.async.commit_group;" ::: "memory")
#define CP_WAIT(N)  asm volatile("cp.async.wait_group %0;" :: "n"(N) : "memory")
#define LDSM4(R, ADDR) \
    asm volatile("ldmatrix.sync.aligned.m8n8.x4.shared.b16 {%0,%1,%2,%3}, [%4];" \
        : "=r"((R)[0]), "=r"((R)[1]), "=r"((R)[2]), "=r"((R)[3]) : "r"(ADDR))
#define MMA16816(C, A, B0, B1) \
    asm volatile("mma.sync.aligned.m16n8k16.row.col.f32.bf16.bf16.f32 " \
        "{%0,%1,%2,%3}, {%4,%5,%6,%7}, {%8,%9}, {%0,%1,%2,%3};" \
        : "+f"((C)[0]), "+f"((C)[1]), "+f"((C)[2]), "+f"((C)[3]) \
        : "r"((A)[0]), "r"((A)[1]), "r"((A)[2]), "r"((A)[3]), "r"(B0), "r"(B1))

__device__ __forceinline__ unsigned pk_bf2(float a, float b) {
    __nv_bfloat162 t;
    t.x = __float2bfloat16_rn(a);
    t.y = __float2bfloat16_rn(b);
    return *reinterpret_cast<unsigned*>(&t);
}
// 8 halves (uint4) -> 8 floats
__device__ __forceinline__ void h8_to_f8(const uint4& r, float* f) {
    const __half2* hp = reinterpret_cast<const __half2*>(&r);
#pragma unroll
    for (int i = 0; i < 4; i++) {
        float2 t = __half22float2(hp[i]);
        f[2 * i] = t.x; f[2 * i + 1] = t.y;
    }
}

// ---------------- CSR build ------------------------------------------------
__global__ void k_count(const int* __restrict__ edge_index) {
    int e = blockIdx.x * blockDim.x + threadIdx.x;
    if (e < EE) atomicAdd(&g_deg[edge_index[EE + e]], 1);
}

__global__ void k_scan() {
    __shared__ int wsums[32];
    __shared__ int carry_s;
    int tid = threadIdx.x, lane = tid & 31, w = tid >> 5;
    if (tid == 0) carry_s = 0;
    __syncthreads();
    for (int base = 0; base < NN; base += 1024) {
        int i = base + tid;
        int v = (i < NN) ? g_deg[i] : 0;
        int inc = v;
#pragma unroll
        for (int o = 1; o < 32; o <<= 1) {
            int t = __shfl_up_sync(0xffffffffu, inc, o);
            if (lane >= o) inc += t;
        }
        if (lane == 31) wsums[w] = inc;
        __syncthreads();
        if (w == 0) {
            int ws = wsums[lane];
#pragma unroll
            for (int o = 1; o < 32; o <<= 1) {
                int t = __shfl_up_sync(0xffffffffu, ws, o);
                if (lane >= o) ws += t;
            }
            wsums[lane] = ws;
        }
        __syncthreads();
        int offset = carry_s + (w ? wsums[w - 1] : 0);
        int exc = offset + inc - v;
        if (i < NN) { g_rowptr[i] = exc; g_wptr[i] = exc; }
        __syncthreads();
        if (tid == 1023) carry_s = offset + inc;
        __syncthreads();
    }
    if (tid == 0) g_rowptr[NN] = carry_s;
}

__global__ void k_scatter(const int* __restrict__ edge_index) {
    int e = blockIdx.x * blockDim.x + threadIdx.x;
    if (e < EE) {
        int src = edge_index[e];
        int dst = edge_index[EE + e];
        g_col[atomicAdd(&g_wptr[dst], 1)] = src;
    }
}

// ---------------- bf16 split conversions -----------------------------------
__global__ void k_split_x(const float* __restrict__ x) {
    int t = blockIdx.x * blockDim.x + threadIdx.x;
    if (t >= NPAD * FIN / 4) return;
    int base = t * 4;
    int row = base >> 7;
    float4 v = (row < NN) ? *(const float4*)(x + base) : make_float4(0.f, 0.f, 0.f, 0.f);
    float a[4] = {v.x, v.y, v.z, v.w};
    float l[4];
#pragma unroll
    for (int i = 0; i < 4; i++)
        l[i] = a[i] - __bfloat162float(__float2bfloat16_rn(a[i]));
    *(uint2*)(g_a1h + base) = make_uint2(pk_bf2(a[0], a[1]), pk_bf2(a[2], a[3]));
    *(uint2*)(g_a1l + base) = make_uint2(pk_bf2(l[0], l[1]), pk_bf2(l[2], l[3]));
}

__global__ void k_split_w(const float* __restrict__ W, __nv_bfloat16* __restrict__ h,
                          __nv_bfloat16* __restrict__ l, int K) {
    int t = blockIdx.x * blockDim.x + threadIdx.x;
    if (t >= 256 * K) return;
    int n = t / K, k = t - n * K;
    float v = W[k * 256 + n];
    __nv_bfloat16 hb = __float2bfloat16_rn(v);
    h[t] = hb;
    l[t] = __float2bfloat16_rn(v - __bfloat162float(hb));
}

// ---------------- HMMA split-bf16 GEMM, fp16 C -----------------------------
#define MBUF 10240
#define MSTAGE (4 * MBUF)
#define MSM_TOTAL (2 * MSTAGE)

__device__ __forceinline__ void stage_chunk(
    uint32_t sb32, int rbase, int nbase, int k0, int K, int tid,
    const __nv_bfloat16* __restrict__ Ah, const __nv_bfloat16* __restrict__ Al,
    const __nv_bfloat16* __restrict__ Bh, const __nv_bfloat16* __restrict__ Bl)
{
#pragma unroll
    for (int t = tid; t < 512; t += 256) {
        int r = t >> 2, seg = t & 3;
        uint32_t so = sb32 + r * 80 + seg * 16;
        size_t ga = (size_t)(rbase + r) * K + k0 + seg * 8;
        size_t gb = (size_t)(nbase + r) * K + k0 + seg * 8;
        CP16(so,             Ah + ga);
        CP16(so + MBUF,      Al + ga);
        CP16(so + 2 * MBUF,  Bh + gb);
        CP16(so + 3 * MBUF,  Bl + gb);
    }
}

__global__ __launch_bounds__(256)
void k_mmagemm(const __nv_bfloat16* __restrict__ Ah, const __nv_bfloat16* __restrict__ Al,
               const __nv_bfloat16* __restrict__ Bh, const __nv_bfloat16* __restrict__ Bl,
               __half* __restrict__ C, int K)
{
    extern __shared__ char sm[];
    uint32_t smb = smem_u32(sm);
    int tid = threadIdx.x, lane = tid & 31, wid = tid >> 5;
    int rbase = blockIdx.x * 128, nbase = blockIdx.y * 128;
    int wm = (wid >> 2) * 64, wn = (wid & 3) * 32;

    float acc[4][4][4];
#pragma unroll
    for (int i = 0; i < 4; i++)
#pragma unroll
        for (int j = 0; j < 4; j++)
#pragma unroll
            for (int q = 0; q < 4; q++) acc[i][j][q] = 0.f;

    int nch = K >> 5;
    stage_chunk(smb, rbase, nbase, 0, K, tid, Ah, Al, Bh, Bl);
    CP_COMMIT();

    int row = lane & 15, kh = lane >> 4;
    for (int ch = 0; ch < nch; ch++) {
        if (ch + 1 < nch) {
            stage_chunk(smb + ((ch + 1) & 1) * MSTAGE, rbase, nbase, (ch + 1) << 5, K, tid,
                        Ah, Al, Bh, Bl);
            CP_COMMIT();
            CP_WAIT(1);
        } else {
            CP_WAIT(0);
        }
        __syncthreads();

        uint32_t s0 = smb + (ch & 1) * MSTAGE;
#pragma unroll
        for (int s = 0; s < 2; s++) {
            int colb = (s * 16 + kh * 8) * 2;
            uint32_t ah[4][4], al[4][4], bh[2][4], bl[2][4];
#pragma unroll
            for (int mi = 0; mi < 4; mi++) {
                uint32_t ad = s0 + (wm + mi * 16 + row) * 80 + colb;
                LDSM4(ah[mi], ad);
                LDSM4(al[mi], ad + MBUF);
            }
#pragma unroll
            for (int bi = 0; bi < 2; bi++) {
                uint32_t ad = s0 + 2 * MBUF + (wn + bi * 16 + row) * 80 + colb;
                LDSM4(bh[bi], ad);
                LDSM4(bl[bi], ad + MBUF);
            }
#pragma unroll
            for (int mi = 0; mi < 4; mi++)
#pragma unroll
                for (int ni = 0; ni < 4; ni++) {
                    int bi = ni >> 1, hf = ni & 1;
                    MMA16816(acc[mi][ni], ah[mi], bh[bi][hf], bh[bi][hf + 2]);
                    MMA16816(acc[mi][ni], ah[mi], bl[bi][hf], bl[bi][hf + 2]);
                    MMA16816(acc[mi][ni], al[mi], bh[bi][hf], bh[bi][hf + 2]);
                }
        }
        __syncthreads();
    }

#pragma unroll
    for (int mi = 0; mi < 4; mi++)
#pragma unroll
        for (int ni = 0; ni < 4; ni++) {
            int r0 = rbase + wm + mi * 16 + (lane >> 2);
            int c  = nbase + wn + ni * 8 + (lane & 3) * 2;
            __half* p = C + (size_t)r0 * 256 + c;
            *(__half2*)p = __floats2half2_rn(acc[mi][ni][0], acc[mi][ni][1]);
            *(__half2*)(p + 8 * 256) = __floats2half2_rn(acc[mi][ni][2], acc[mi][ni][3]);
        }
}

// ---------------- attention logits per node (fp16 xw) ----------------------
template<int H, int C>
__global__ void k_al(const __half* __restrict__ xw, const float* __restrict__ a_src,
                     const float* __restrict__ a_dst,
                     float* __restrict__ als, float* __restrict__ ald)
{
    int gw = (blockIdx.x * blockDim.x + threadIdx.x) >> 5;
    int lane = threadIdx.x & 31;
    if (gw >= NN * H) return;
    int n = gw / H, h = gw % H;
    const __half2* row = (const __half2*)(xw + (size_t)n * (H * C) + h * C);
    float s = 0.f, d = 0.f;
    for (int c2 = lane; c2 < C / 2; c2 += 32) {
        float2 v = __half22float2(row[c2]);
        s += v.x * a_src[h * C + 2 * c2] + v.y * a_src[h * C + 2 * c2 + 1];
        d += v.x * a_dst[h * C + 2 * c2] + v.y * a_dst[h * C + 2 * c2 + 1];
    }
#pragma unroll
    for (int o = 16; o; o >>= 1) {
        s += __shfl_down_sync(0xffffffffu, s, o);
        d += __shfl_down_sync(0xffffffffu, d, o);
    }
    if (lane == 0) { als[n * H + h] = s; ald[n * H + h] = d; }
}

// ---------------- warp-per-node softmax aggregation (fp16 gather) ----------
template<int H, bool ELU, bool SPLIT>
__global__ __launch_bounds__(256)
void k_agg_w(const __half* __restrict__ xw, const float* __restrict__ als,
             const float* __restrict__ ald, const float* __restrict__ bias,
             __half* __restrict__ outh, float* __restrict__ ssout,
             __nv_bfloat16* __restrict__ sph, __nv_bfloat16* __restrict__ spl)
{
    int gw = (blockIdx.x * blockDim.x + threadIdx.x) >> 5;
    int lane = threadIdx.x & 31;
    if (gw >= NN) return;
    int n = gw;
    int beg = g_rowptr[n];
    int deg = g_rowptr[n + 1] - beg;

    const int myh = (lane * H) >> 5;
    const float admy = ald[(size_t)n * H + myh];

    float eself = als[(size_t)n * H + myh] + admy;
    eself = eself > 0.f ? eself : NEG_SLOPE * eself;
    float exs = __expf(eself);
    float den = exs;

    float acc[8];
    {
        uint4 raw = *(const uint4*)(xw + (size_t)n * 256 + (lane << 3));
        float f[8]; h8_to_f8(raw, f);
#pragma unroll
        for (int t = 0; t < 8; t++) acc[t] = exs * f[t];
    }

    for (int base = 0; base < deg; base += 32) {
        int idx = base + lane;
        int scol = (idx < deg) ? g_col[beg + idx] : 0;
        int cn = min(32, deg - base);
#pragma unroll 4
        for (int jj = 0; jj < cn; jj++) {
            int s = __shfl_sync(0xffffffffu, scol, jj);
            float e = als[(size_t)s * H + myh] + admy;
            e = e > 0.f ? e : NEG_SLOPE * e;
            float ex = __expf(e);
            den += ex;
            uint4 raw = *(const uint4*)(xw + (size_t)s * 256 + (lane << 3));
            float f[8]; h8_to_f8(raw, f);
#pragma unroll
            for (int t = 0; t < 8; t++) acc[t] += ex * f[t];
        }
    }

    float invd = 1.f / den;
    const float4* bb = (const float4*)(bias + (lane << 3));
    float4 b0 = bb[0], b1 = bb[1];
    float o[8];
    o[0] = acc[0] * invd + b0.x; o[1] = acc[1] * invd + b0.y;
    o[2] = acc[2] * invd + b0.z; o[3] = acc[3] * invd + b0.w;
    o[4] = acc[4] * invd + b1.x; o[5] = acc[5] * invd + b1.y;
    o[6] = acc[6] * invd + b1.z; o[7] = acc[7] * invd + b1.w;
    float ssq = 0.f;
#pragma unroll
    for (int t = 0; t < 8; t++) {
        if (ELU) o[t] = o[t] > 0.f ? o[t] : expm1f(o[t]);
        ssq += o[t] * o[t];
    }
    // fp16 emb for the loss
    {
        uint4 ho;
        __half2* hp = (__half2*)&ho;
        hp[0] = __floats2half2_rn(o[0], o[1]);
        hp[1] = __floats2half2_rn(o[2], o[3]);
        hp[2] = __floats2half2_rn(o[4], o[5]);
        hp[3] = __floats2half2_rn(o[6], o[7]);
        *(uint4*)(outh + (size_t)n * 256 + (lane << 3)) = ho;
    }
    if (SPLIT) {
        unsigned hh[4], ll[4];
#pragma unroll
        for (int t2 = 0; t2 < 4; t2++) {
            float a = o[2 * t2], b = o[2 * t2 + 1];
            float la = a - __bfloat162float(__float2bfloat16_rn(a));
            float lb = b - __bfloat162float(__float2bfloat16_rn(b));
            hh[t2] = pk_bf2(a, b);
            ll[t2] = pk_bf2(la, lb);
        }
        *(uint4*)(sph + (size_t)n * 256 + (lane << 3)) = make_uint4(hh[0], hh[1], hh[2], hh[3]);
        *(uint4*)(spl + (size_t)n * 256 + (lane << 3)) = make_uint4(ll[0], ll[1], ll[2], ll[3]);
    }
#pragma unroll
    for (int oo = 16; oo; oo >>= 1) ssq += __shfl_xor_sync(0xffffffffu, ssq, oo);
    if (lane == 0) ssout[n] = ssq;
}

// ---------------- inverse norms --------------------------------------------
__global__ void k_inv()
{
    int i = blockIdx.x * blockDim.x + threadIdx.x;
    if (i < NN) g_inv[i] = 1.f / fmaxf(sqrtf(g_ss1[i] + g_ss2[i]), 1e-8f);
}

// ---------------- contrastive loss: block per walk, fp16 gathers -----------
#define SMEM_EMB_F4 (WALK_LEN * 128)
#define SMEM_LOSS_BYTES (SMEM_EMB_F4 * 16 + WALK_LEN * 4 + WALK_LEN * 4 + 16 * 4)

__device__ __forceinline__ float dot16(const float4& a0, const float4& a1,
                                       const float4& a2, const float4& a3,
                                       const float4& p0, const float4& p1,
                                       const float4& p2, const float4& p3)
{
    float s = a0.x * p0.x + a0.y * p0.y + a0.z * p0.z + a0.w * p0.w
            + a1.x * p1.x + a1.y * p1.y + a1.z * p1.z + a1.w * p1.w
            + a2.x * p2.x + a2.y * p2.y + a2.z * p2.z + a2.w * p2.w
            + a3.x * p3.x + a3.y * p3.y + a3.z * p3.z + a3.w * p3.w;
#pragma unroll
    for (int o = 16; o; o >>= 1) s += __shfl_xor_sync(0xffffffffu, s, o);
    return s;
}
__device__ __forceinline__ float4 h4_to_f4(uint2 r) {
    const __half2* hp = reinterpret_cast<const __half2*>(&r);
    float2 a = __half22float2(hp[0]), b = __half22float2(hp[1]);
    return make_float4(a.x, a.y, b.x, b.y);
}

__global__ __launch_bounds__(512)
void k_loss(const int* __restrict__ walks, const int* __restrict__ negs)
{
    extern __shared__ char smraw[];
    float4* sm4   = (float4*)smraw;
    int*    ids_s = (int*)(smraw + SMEM_EMB_F4 * 16);
    float*  inv_s = (float*)(smraw + SMEM_EMB_F4 * 16 + WALK_LEN * 4);
    float*  wsum  = (float*)(smraw + SMEM_EMB_F4 * 16 + WALK_LEN * 8);

    int b = blockIdx.x;
    int tid = threadIdx.x, lane = tid & 31, w = tid >> 5;

    if (tid < WALK_LEN) {
        int id = walks[b * WALK_LEN + tid];
        ids_s[tid] = id;
        inv_s[tid] = g_inv[id];
    }
    __syncthreads();

    // 64 rows x 512 dims (fp16 -> normalized fp32 smem)
    for (int f = tid; f < WALK_LEN * 64; f += 512) {   // f = one uint4 (8 halves)
        int r = f >> 6, q = f & 63;
        int id = ids_s[r];
        float iv = inv_s[r];
        uint4 raw = (q < 32) ? *(const uint4*)(g_e1h + (size_t)id * 256 + q * 8)
                             : *(const uint4*)(g_e2h + (size_t)id * 256 + (q - 32) * 8);
        float fv[8]; h8_to_f8(raw, fv);
        sm4[r * 128 + 2 * q]     = make_float4(fv[0] * iv, fv[1] * iv, fv[2] * iv, fv[3] * iv);
        sm4[r * 128 + 2 * q + 1] = make_float4(fv[4] * iv, fv[5] * iv, fv[6] * iv, fv[7] * iv);
    }
    __syncthreads();

    float term_acc = 0.f;
    for (int k = 0; k < 4; k++) {
        int l = (w << 2) | k;
        const float4* ar = sm4 + (size_t)l * 128;
        float4 A0 = ar[lane], A1 = ar[32 + lane], A2 = ar[64 + lane], A3 = ar[96 + lane];

        int posid[2 * WINDOW];
        bool pval[2 * WINDOW];
        float pos_sum = 0.f;
#pragma unroll
        for (int p = 0; p < 2 * WINDOW; p++) {
            int off = (p < WINDOW) ? (p - WINDOW) : (p - WINDOW + 1);
            int pp = l + off;
            bool val = (pp >= 0) && (pp < WALK_LEN);
            int ppc = min(max(pp, 0), WALK_LEN - 1);
            pval[p] = val;
            posid[p] = ids_s[ppc];
            const float4* pr = sm4 + (size_t)ppc * 128;
            float4 P0 = pr[lane], P1 = pr[32 + lane], P2 = pr[64 + lane], P3 = pr[96 + lane];
            float d = dot16(A0, A1, A2, A3, P0, P1, P2, P3);
            if (val) pos_sum += __expf(d * INV_TEMP);
        }

        int nbase = (b * WALK_LEN + l) * NEG_S;
        int ngl = (lane < NEG_S) ? negs[nbase + lane] : 0;
        float neg_sum = 0.f;
#pragma unroll
        for (int s = 0; s < NEG_S; s++) {
            int ng = __shfl_sync(0xffffffffu, ngl, s);
            bool inpos = false;
#pragma unroll
            for (int p = 0; p < 2 * WINDOW; p++)
                inpos = inpos || (pval[p] && (ng == posid[p]));
            const __half* n1 = g_e1h + (size_t)ng * 256;
            const __half* n2 = g_e2h + (size_t)ng * 256;
            float4 P0 = h4_to_f4(*(const uint2*)(n1 + 4 * lane));
            float4 P1 = h4_to_f4(*(const uint2*)(n1 + 128 + 4 * lane));
            float4 P2 = h4_to_f4(*(const uint2*)(n2 + 4 * lane));
            float4 P3 = h4_to_f4(*(const uint2*)(n2 + 128 + 4 * lane));
            float d = dot16(A0, A1, A2, A3, P0, P1, P2, P3);
            float sim = d * g_inv[ng] * INV_TEMP;
            if (!inpos) neg_sum += __expf(sim);
        }
        term_acc += log1pf(neg_sum / pos_sum);
    }

    if (lane == 0) wsum[w] = term_acc;
    __syncthreads();
    if (w == 0) {
        float s = (lane < 16) ? wsum[lane] : 0.f;
#pragma unroll
        for (int o = 16; o; o >>= 1) s += __shfl_xor_sync(0xffffffffu, s, o);
        if (lane == 0) g_terms[b] = s;
    }
}

__global__ void k_reduce(float* __restrict__ out)
{
    __shared__ float sh[512];
    int tid = threadIdx.x;
    sh[tid] = (tid < NUM_WALKS) ? g_terms[tid] : 0.f;
    __syncthreads();
    for (int o = 256; o; o >>= 1) {
        if (tid < o) sh[tid] += sh[tid + o];
        __syncthreads();
    }
    if (tid == 0) out[0] = sh[0];
}

// ---------------- driver ---------------------------------------------------
extern "C" void kernel_launch(void* const* d_in, const int* in_sizes, int n_in,
                              void* d_out, int out_size)
{
    const float* x          = (const float*)d_in[0];
    const int*   edge_index = (const int*)  d_in[1];
    const int*   walks      = (const int*)  d_in[2];
    const int*   negs       = (const int*)  d_in[3];
    const float* W1         = (const float*)d_in[4];
    const float* a_src1     = (const float*)d_in[5];
    const float* a_dst1     = (const float*)d_in[6];
    const float* b1         = (const float*)d_in[7];
    const float* W2         = (const float*)d_in[8];
    const float* a_src2     = (const float*)d_in[9];
    const float* a_dst2     = (const float*)d_in[10];
    const float* b2         = (const float*)d_in[11];
    float* out = (float*)d_out;

    float *als1, *ald1, *als2, *ald2, *ss1, *ss2;
    __half *xw1h, *xw2h, *e1h, *e2h;
    __nv_bfloat16 *a1h, *a1l, *a2h, *a2l, *bw1h, *bw1l, *bw2h, *bw2l;
    void* degp;
    cudaGetSymbolAddress((void**)&xw1h, g_xw1h);
    cudaGetSymbolAddress((void**)&xw2h, g_xw2h);
    cudaGetSymbolAddress((void**)&e1h,  g_e1h);
    cudaGetSymbolAddress((void**)&e2h,  g_e2h);
    cudaGetSymbolAddress((void**)&als1, g_als1);
    cudaGetSymbolAddress((void**)&ald1, g_ald1);
    cudaGetSymbolAddress((void**)&als2, g_als2);
    cudaGetSymbolAddress((void**)&ald2, g_ald2);
    cudaGetSymbolAddress((void**)&ss1,  g_ss1);
    cudaGetSymbolAddress((void**)&ss2,  g_ss2);
    cudaGetSymbolAddress((void**)&a1h,  g_a1h);
    cudaGetSymbolAddress((void**)&a1l,  g_a1l);
    cudaGetSymbolAddress((void**)&a2h,  g_a2h);
    cudaGetSymbolAddress((void**)&a2l,  g_a2l);
    cudaGetSymbolAddress((void**)&bw1h, g_b1h);
    cudaGetSymbolAddress((void**)&bw1l, g_b1l);
    cudaGetSymbolAddress((void**)&bw2h, g_b2h);
    cudaGetSymbolAddress((void**)&bw2l, g_b2l);
    cudaGetSymbolAddress(&degp, g_deg);

    static int attr_set = 0;
    if (!attr_set) {
        cudaFuncSetAttribute(k_loss, cudaFuncAttributeMaxDynamicSharedMemorySize,
                             SMEM_LOSS_BYTES);
        cudaFuncSetAttribute(k_mmagemm, cudaFuncAttributeMaxDynamicSharedMemorySize,
                             MSM_TOTAL);
        attr_set = 1;
    }

    // CSR build
    cudaMemsetAsync(degp, 0, NN * sizeof(int));
    k_count<<<(EE + 255) / 256, 256>>>(edge_index);
    k_scan<<<1, 1024>>>();
    k_scatter<<<(EE + 255) / 256, 256>>>(edge_index);

    // operand conversions
    k_split_x<<<(NPAD * FIN / 4 + 255) / 256, 256>>>(x);
    k_split_w<<<(256 * FIN + 255) / 256, 256>>>(W1, bw1h, bw1l, FIN);
    k_split_w<<<(256 * H1 + 255) / 256, 256>>>(W2, bw2h, bw2l, H1);

    // layer 1
    k_mmagemm<<<dim3(NPAD / 128, 2), 256, MSM_TOTAL>>>(a1h, a1l, bw1h, bw1l, xw1h, FIN);
    k_al<NHEADS, HID><<<(NN * NHEADS * 32 + 255) / 256, 256>>>(xw1h, a_src1, a_dst1, als1, ald1);
    k_agg_w<NHEADS, true, true><<<(NN * 32 + 255) / 256, 256>>>(xw1h, als1, ald1, b1, e1h, ss1, a2h, a2l);

    // layer 2
    k_mmagemm<<<dim3(NPAD / 128, 2), 256, MSM_TOTAL>>>(a2h, a2l, bw2h, bw2l, xw2h, H1);
    k_al<1, H1><<<(NN * 32 + 255) / 256, 256>>>(xw2h, a_src2, a_dst2, als2, ald2);
    k_agg_w<1, false, false><<<(NN * 32 + 255) / 256, 256>>>(xw2h, als2, ald2, b2, e2h, ss2, nullptr, nullptr);

    // loss
    k_inv<<<(NN + 255) / 256, 256>>>();
    k_loss<<<NUM_WALKS, 512, SMEM_LOSS_BYTES>>>(walks, negs);
    k_reduce<<<1, 512>>>(out);
}

// round 7
// speedup vs baseline: 2.3912x; 1.1061x over previous
#include <cuda_runtime.h>
#include <cuda_bf16.h>
#include <cuda_fp16.h>
#include <cstdint>

#define NN 50000
#define NPAD 50048
#define EE 800000
#define FIN 128
#define HID 32
#define NHEADS 8
#define H1 256
#define NUM_WALKS 512
#define WALK_LEN 64
#define WINDOW 5
#define NEG_S 10
#define NEG_SLOPE 0.2f
#define INV_TEMP (1.0f/0.07f)

// ---------------- scratch (device globals; no cudaMalloc allowed) ----------
__device__ __half g_xw1h[(size_t)NPAD * H1];   // fp16 xw (gather)
__device__ __half g_xw2h[(size_t)NPAD * H1];
__device__ __half g_e1h[(size_t)NN * H1];      // fp16 emb (loss gathers)
__device__ __half g_e2h[(size_t)NN * H1];
__device__ float g_als1[(size_t)NPAD * NHEADS];
__device__ float g_ald1[(size_t)NPAD * NHEADS];
__device__ float g_als2[NN];
__device__ float g_ald2[NN];
__device__ float g_alpS[8 * NPAD];   // layer-2 al partials (slot-major)
__device__ float g_alpD[8 * NPAD];
__device__ float g_ss1[NN];
__device__ float g_ss2[NN];
__device__ float g_inv[NN];
__device__ int   g_deg[NN];
__device__ int   g_rowptr[NN + 1];
__device__ int   g_wptr[NN];
__device__ int   g_col[EE];
__device__ float g_terms[NUM_WALKS];
// bf16 split operands (zero-init; pad rows stay zero)
__device__ __nv_bfloat16 g_a1h[(size_t)NPAD * FIN];
__device__ __nv_bfloat16 g_a1l[(size_t)NPAD * FIN];
__device__ __nv_bfloat16 g_a2h[(size_t)NPAD * H1];
__device__ __nv_bfloat16 g_a2l[(size_t)NPAD * H1];
__device__ __nv_bfloat16 g_b1h[256 * FIN];
__device__ __nv_bfloat16 g_b1l[256 * FIN];
__device__ __nv_bfloat16 g_b2h[256 * H1];
__device__ __nv_bfloat16 g_b2l[256 * H1];

// ---------------- PTX helpers (arch-generic sm_80+) ------------------------
__device__ __forceinline__ uint32_t smem_u32(const void* p) {
    uint32_t a;
    asm("{ .reg .u64 t; cvta.to.shared.u64 t, %1; cvt.u32.u64 %0, t; }" : "=r"(a) : "l"(p));
    return a;
}
#define CP16(SADDR, GPTR) \
    asm volatile("cp.async.cg.shared.global [%0], [%1], 16;" :: "r"(SADDR), "l"(GPTR))
#define CP_COMMIT() asm volatile("cp.async.commit_group;" ::: "memory")
#define CP_WAIT(N)  asm volatile("cp.async.wait_group %0;" :: "n"(N) : "memory")
#define LDSM4(R, ADDR) \
    asm volatile("ldmatrix.sync.aligned.m8n8.x4.shared.b16 {%0,%1,%2,%3}, [%4];" \
        : "=r"((R)[0]), "=r"((R)[1]), "=r"((R)[2]), "=r"((R)[3]) : "r"(ADDR))
#define MMA16816(C, A, B0, B1) \
    asm volatile("mma.sync.aligned.m16n8k16.row.col.f32.bf16.bf16.f32 " \
        "{%0,%1,%2,%3}, {%4,%5,%6,%7}, {%8,%9}, {%0,%1,%2,%3};" \
        : "+f"((C)[0]), "+f"((C)[1]), "+f"((C)[2]), "+f"((C)[3]) \
        : "r"((A)[0]), "r"((A)[1]), "r"((A)[2]), "r"((A)[3]), "r"(B0), "r"(B1))

__device__ __forceinline__ unsigned pk_bf2(float a, float b) {
    __nv_bfloat162 t;
    t.x = __float2bfloat16_rn(a);
    t.y = __float2bfloat16_rn(b);
    return *reinterpret_cast<unsigned*>(&t);
}
__device__ __forceinline__ void h8_to_f8(const uint4& r, float* f) {
    const __half2* hp = reinterpret_cast<const __half2*>(&r);
#pragma unroll
    for (int i = 0; i < 4; i++) {
        float2 t = __half22float2(hp[i]);
        f[2 * i] = t.x; f[2 * i + 1] = t.y;
    }
}

// ---------------- CSR build ------------------------------------------------
__global__ void k_count(const int* __restrict__ edge_index) {
    int e = blockIdx.x * blockDim.x + threadIdx.x;
    if (e < EE) atomicAdd(&g_deg[edge_index[EE + e]], 1);
}

__global__ void k_scan() {   // single block, 1024 threads, 4 items/thread
    __shared__ int wsums[32];
    __shared__ int carry_s;
    int tid = threadIdx.x, lane = tid & 31, w = tid >> 5;
    if (tid == 0) carry_s = 0;
    __syncthreads();
    for (int base = 0; base < NN; base += 4096) {
        int i0 = base + tid * 4;
        int v[4];
        if (i0 + 4 <= NN) {
            int4 q = *(const int4*)(g_deg + i0);
            v[0] = q.x; v[1] = q.y; v[2] = q.z; v[3] = q.w;
        } else {
#pragma unroll
            for (int j = 0; j < 4; j++) v[j] = (i0 + j < NN) ? g_deg[i0 + j] : 0;
        }
        int tsum = v[0] + v[1] + v[2] + v[3];
        int inc = tsum;
#pragma unroll
        for (int o = 1; o < 32; o <<= 1) {
            int t = __shfl_up_sync(0xffffffffu, inc, o);
            if (lane >= o) inc += t;
        }
        if (lane == 31) wsums[w] = inc;
        __syncthreads();
        if (w == 0) {
            int ws = wsums[lane];
#pragma unroll
            for (int o = 1; o < 32; o <<= 1) {
                int t = __shfl_up_sync(0xffffffffu, ws, o);
                if (lane >= o) ws += t;
            }
            wsums[lane] = ws;
        }
        __syncthreads();
        int offset = carry_s + (w ? wsums[w - 1] : 0) + inc - tsum;
        int e0 = offset, e1 = e0 + v[0], e2 = e1 + v[1], e3 = e2 + v[2];
        if (i0 < NN)     { g_rowptr[i0]     = e0; g_wptr[i0]     = e0; }
        if (i0 + 1 < NN) { g_rowptr[i0 + 1] = e1; g_wptr[i0 + 1] = e1; }
        if (i0 + 2 < NN) { g_rowptr[i0 + 2] = e2; g_wptr[i0 + 2] = e2; }
        if (i0 + 3 < NN) { g_rowptr[i0 + 3] = e3; g_wptr[i0 + 3] = e3; }
        __syncthreads();
        if (tid == 1023) carry_s = offset + tsum;
        __syncthreads();
    }
    if (tid == 0) g_rowptr[NN] = carry_s;
}

__global__ void k_scatter(const int* __restrict__ edge_index) {
    int e = blockIdx.x * blockDim.x + threadIdx.x;
    if (e < EE) {
        int src = edge_index[e];
        int dst = edge_index[EE + e];
        g_col[atomicAdd(&g_wptr[dst], 1)] = src;
    }
}

// ---------------- bf16 split conversions -----------------------------------
__global__ void k_split_x(const float* __restrict__ x) {
    int t = blockIdx.x * blockDim.x + threadIdx.x;
    if (t >= NPAD * FIN / 4) return;
    int base = t * 4;
    int row = base >> 7;
    float4 v = (row < NN) ? *(const float4*)(x + base) : make_float4(0.f, 0.f, 0.f, 0.f);
    float a[4] = {v.x, v.y, v.z, v.w};
    float l[4];
#pragma unroll
    for (int i = 0; i < 4; i++)
        l[i] = a[i] - __bfloat162float(__float2bfloat16_rn(a[i]));
    *(uint2*)(g_a1h + base) = make_uint2(pk_bf2(a[0], a[1]), pk_bf2(a[2], a[3]));
    *(uint2*)(g_a1l + base) = make_uint2(pk_bf2(l[0], l[1]), pk_bf2(l[2], l[3]));
}

__global__ void k_split_w(const float* __restrict__ W, __nv_bfloat16* __restrict__ h,
                          __nv_bfloat16* __restrict__ l, int K) {
    int t = blockIdx.x * blockDim.x + threadIdx.x;
    if (t >= 256 * K) return;
    int n = t / K, k = t - n * K;
    float v = W[k * 256 + n];
    __nv_bfloat16 hb = __float2bfloat16_rn(v);
    h[t] = hb;
    l[t] = __float2bfloat16_rn(v - __bfloat162float(hb));
}

// ---------------- HMMA split-bf16 GEMM, fp16 C, fused al epilogue ----------
// FOLD=1: per-head (H=8) al fold, direct write.  FOLD=2: H=1, slot partials.
#define MBUF 10240
#define MSTAGE (4 * MBUF)
#define MSM_TOTAL (2 * MSTAGE)

__device__ __forceinline__ void stage_chunk(
    uint32_t sb32, int rbase, int nbase, int k0, int K, int tid,
    const __nv_bfloat16* __restrict__ Ah, const __nv_bfloat16* __restrict__ Al,
    const __nv_bfloat16* __restrict__ Bh, const __nv_bfloat16* __restrict__ Bl)
{
#pragma unroll
    for (int t = tid; t < 512; t += 256) {
        int r = t >> 2, seg = t & 3;
        uint32_t so = sb32 + r * 80 + seg * 16;
        size_t ga = (size_t)(rbase + r) * K + k0 + seg * 8;
        size_t gb = (size_t)(nbase + r) * K + k0 + seg * 8;
        CP16(so,             Ah + ga);
        CP16(so + MBUF,      Al + ga);
        CP16(so + 2 * MBUF,  Bh + gb);
        CP16(so + 3 * MBUF,  Bl + gb);
    }
}

template<int FOLD>
__global__ __launch_bounds__(256)
void k_mmagemm(const __nv_bfloat16* __restrict__ Ah, const __nv_bfloat16* __restrict__ Al,
               const __nv_bfloat16* __restrict__ Bh, const __nv_bfloat16* __restrict__ Bl,
               __half* __restrict__ C, int K,
               const float* __restrict__ avs, const float* __restrict__ avd,
               float* __restrict__ foldS, float* __restrict__ foldD)
{
    extern __shared__ char sm[];
    uint32_t smb = smem_u32(sm);
    int tid = threadIdx.x, lane = tid & 31, wid = tid >> 5;
    int rbase = blockIdx.x * 128, nbase = blockIdx.y * 128;
    int wm = (wid >> 2) * 64, wn = (wid & 3) * 32;

    float acc[4][4][4];
#pragma unroll
    for (int i = 0; i < 4; i++)
#pragma unroll
        for (int j = 0; j < 4; j++)
#pragma unroll
            for (int q = 0; q < 4; q++) acc[i][j][q] = 0.f;

    int nch = K >> 5;
    stage_chunk(smb, rbase, nbase, 0, K, tid, Ah, Al, Bh, Bl);
    CP_COMMIT();

    int row = lane & 15, kh = lane >> 4;
    for (int ch = 0; ch < nch; ch++) {
        if (ch + 1 < nch) {
            stage_chunk(smb + ((ch + 1) & 1) * MSTAGE, rbase, nbase, (ch + 1) << 5, K, tid,
                        Ah, Al, Bh, Bl);
            CP_COMMIT();
            CP_WAIT(1);
        } else {
            CP_WAIT(0);
        }
        __syncthreads();

        uint32_t s0 = smb + (ch & 1) * MSTAGE;
#pragma unroll
        for (int s = 0; s < 2; s++) {
            int colb = (s * 16 + kh * 8) * 2;
            uint32_t ah[4][4], al[4][4], bh[2][4], bl[2][4];
#pragma unroll
            for (int mi = 0; mi < 4; mi++) {
                uint32_t ad = s0 + (wm + mi * 16 + row) * 80 + colb;
                LDSM4(ah[mi], ad);
                LDSM4(al[mi], ad + MBUF);
            }
#pragma unroll
            for (int bi = 0; bi < 2; bi++) {
                uint32_t ad = s0 + 2 * MBUF + (wn + bi * 16 + row) * 80 + colb;
                LDSM4(bh[bi], ad);
                LDSM4(bl[bi], ad + MBUF);
            }
#pragma unroll
            for (int mi = 0; mi < 4; mi++)
#pragma unroll
                for (int ni = 0; ni < 4; ni++) {
                    int bi = ni >> 1, hf = ni & 1;
                    MMA16816(acc[mi][ni], ah[mi], bh[bi][hf], bh[bi][hf + 2]);
                    MMA16816(acc[mi][ni], ah[mi], bl[bi][hf], bl[bi][hf + 2]);
                    MMA16816(acc[mi][ni], al[mi], bh[bi][hf], bh[bi][hf + 2]);
                }
        }
        __syncthreads();
    }

#pragma unroll
    for (int mi = 0; mi < 4; mi++)
#pragma unroll
        for (int ni = 0; ni < 4; ni++) {
            int r0 = rbase + wm + mi * 16 + (lane >> 2);
            int c  = nbase + wn + ni * 8 + (lane & 3) * 2;
            __half* p = C + (size_t)r0 * 256 + c;
            *(__half2*)p = __floats2half2_rn(acc[mi][ni][0], acc[mi][ni][1]);
            *(__half2*)(p + 8 * 256) = __floats2half2_rn(acc[mi][ni][2], acc[mi][ni][3]);
        }

    // fused attention-logit fold: al = acc-row . a_vec
    {
        int h = (nbase + wn) >> 5;                 // FOLD==1: head of this warp
        int slot = blockIdx.y * 4 + (wid & 3);     // FOLD==2: partial slot
#pragma unroll
        for (int mi = 0; mi < 4; mi++) {
            float ps0 = 0.f, ps1 = 0.f, pd0 = 0.f, pd1 = 0.f;
#pragma unroll
            for (int ni = 0; ni < 4; ni++) {
                int cc = ni * 8 + (lane & 3) * 2;
                float s0, s1, d0, d1;
                if (FOLD == 1) {
                    s0 = avs[h * 32 + cc]; s1 = avs[h * 32 + cc + 1];
                    d0 = avd[h * 32 + cc]; d1 = avd[h * 32 + cc + 1];
                } else {
                    int c = nbase + wn + cc;
                    s0 = avs[c]; s1 = avs[c + 1];
                    d0 = avd[c]; d1 = avd[c + 1];
                }
                ps0 += acc[mi][ni][0] * s0 + acc[mi][ni][1] * s1;
                ps1 += acc[mi][ni][2] * s0 + acc[mi][ni][3] * s1;
                pd0 += acc[mi][ni][0] * d0 + acc[mi][ni][1] * d1;
                pd1 += acc[mi][ni][2] * d0 + acc[mi][ni][3] * d1;
            }
#pragma unroll
            for (int o = 1; o <= 2; o <<= 1) {
                ps0 += __shfl_xor_sync(0xffffffffu, ps0, o);
                ps1 += __shfl_xor_sync(0xffffffffu, ps1, o);
                pd0 += __shfl_xor_sync(0xffffffffu, pd0, o);
                pd1 += __shfl_xor_sync(0xffffffffu, pd1, o);
            }
            if ((lane & 3) == 0) {
                int r0 = rbase + wm + mi * 16 + (lane >> 2);
                if (FOLD == 1) {
                    foldS[(size_t)r0 * 8 + h] = ps0;
                    foldS[(size_t)(r0 + 8) * 8 + h] = ps1;
                    foldD[(size_t)r0 * 8 + h] = pd0;
                    foldD[(size_t)(r0 + 8) * 8 + h] = pd1;
                } else {
                    foldS[(size_t)slot * NPAD + r0] = ps0;
                    foldS[(size_t)slot * NPAD + r0 + 8] = ps1;
                    foldD[(size_t)slot * NPAD + r0] = pd0;
                    foldD[(size_t)slot * NPAD + r0 + 8] = pd1;
                }
            }
        }
    }
}

// sum the 8 layer-2 al partial slots (deterministic)
__global__ void k_alsum2()
{
    int i = blockIdx.x * blockDim.x + threadIdx.x;
    if (i >= NN) return;
    float s = 0.f, d = 0.f;
#pragma unroll
    for (int k = 0; k < 8; k++) {
        s += g_alpS[(size_t)k * NPAD + i];
        d += g_alpD[(size_t)k * NPAD + i];
    }
    g_als2[i] = s;
    g_ald2[i] = d;
}

// ---------------- warp-per-node softmax aggregation (fp16 gather) ----------
template<int H, bool ELU, bool SPLIT>
__global__ __launch_bounds__(256)
void k_agg_w(const __half* __restrict__ xw, const float* __restrict__ als,
             const float* __restrict__ ald, const float* __restrict__ bias,
             __half* __restrict__ outh, float* __restrict__ ssout,
             __nv_bfloat16* __restrict__ sph, __nv_bfloat16* __restrict__ spl)
{
    int gw = (blockIdx.x * blockDim.x + threadIdx.x) >> 5;
    int lane = threadIdx.x & 31;
    if (gw >= NN) return;
    int n = gw;
    int beg = g_rowptr[n];
    int deg = g_rowptr[n + 1] - beg;

    const int myh = (lane * H) >> 5;
    const float admy = ald[(size_t)n * H + myh];

    float eself = als[(size_t)n * H + myh] + admy;
    eself = eself > 0.f ? eself : NEG_SLOPE * eself;
    float exs = __expf(eself);
    float den = exs;

    float acc[8];
    {
        uint4 raw = *(const uint4*)(xw + (size_t)n * 256 + (lane << 3));
        float f[8]; h8_to_f8(raw, f);
#pragma unroll
        for (int t = 0; t < 8; t++) acc[t] = exs * f[t];
    }

    for (int base = 0; base < deg; base += 32) {
        int idx = base + lane;
        int scol = (idx < deg) ? g_col[beg + idx] : 0;
        int cn = min(32, deg - base);
#pragma unroll 4
        for (int jj = 0; jj < cn; jj++) {
            int s = __shfl_sync(0xffffffffu, scol, jj);
            float e = als[(size_t)s * H + myh] + admy;
            e = e > 0.f ? e : NEG_SLOPE * e;
            float ex = __expf(e);
            den += ex;
            uint4 raw = *(const uint4*)(xw + (size_t)s * 256 + (lane << 3));
            float f[8]; h8_to_f8(raw, f);
#pragma unroll
            for (int t = 0; t < 8; t++) acc[t] += ex * f[t];
        }
    }

    float invd = 1.f / den;
    const float4* bb = (const float4*)(bias + (lane << 3));
    float4 b0 = bb[0], b1 = bb[1];
    float o[8];
    o[0] = acc[0] * invd + b0.x; o[1] = acc[1] * invd + b0.y;
    o[2] = acc[2] * invd + b0.z; o[3] = acc[3] * invd + b0.w;
    o[4] = acc[4] * invd + b1.x; o[5] = acc[5] * invd + b1.y;
    o[6] = acc[6] * invd + b1.z; o[7] = acc[7] * invd + b1.w;
    float ssq = 0.f;
#pragma unroll
    for (int t = 0; t < 8; t++) {
        if (ELU) o[t] = o[t] > 0.f ? o[t] : expm1f(o[t]);
        ssq += o[t] * o[t];
    }
    {
        uint4 ho;
        __half2* hp = (__half2*)&ho;
        hp[0] = __floats2half2_rn(o[0], o[1]);
        hp[1] = __floats2half2_rn(o[2], o[3]);
        hp[2] = __floats2half2_rn(o[4], o[5]);
        hp[3] = __floats2half2_rn(o[6], o[7]);
        *(uint4*)(outh + (size_t)n * 256 + (lane << 3)) = ho;
    }
    if (SPLIT) {
        unsigned hh[4], ll[4];
#pragma unroll
        for (int t2 = 0; t2 < 4; t2++) {
            float a = o[2 * t2], b = o[2 * t2 + 1];
            float la = a - __bfloat162float(__float2bfloat16_rn(a));
            float lb = b - __bfloat162float(__float2bfloat16_rn(b));
            hh[t2] = pk_bf2(a, b);
            ll[t2] = pk_bf2(la, lb);
        }
        *(uint4*)(sph + (size_t)n * 256 + (lane << 3)) = make_uint4(hh[0], hh[1], hh[2], hh[3]);
        *(uint4*)(spl + (size_t)n * 256 + (lane << 3)) = make_uint4(ll[0], ll[1], ll[2], ll[3]);
    }
#pragma unroll
    for (int oo = 16; oo; oo >>= 1) ssq += __shfl_xor_sync(0xffffffffu, ssq, oo);
    if (lane == 0) ssout[n] = ssq;
}

// ---------------- inverse norms --------------------------------------------
__global__ void k_inv()
{
    int i = blockIdx.x * blockDim.x + threadIdx.x;
    if (i < NN) g_inv[i] = 1.f / fmaxf(sqrtf(g_ss1[i] + g_ss2[i]), 1e-8f);
}

// ---------------- contrastive loss: block per walk, fp16 gathers -----------
#define SMEM_EMB_F4 (WALK_LEN * 128)
#define SMEM_LOSS_BYTES (SMEM_EMB_F4 * 16 + WALK_LEN * 4 + WALK_LEN * 4 + 16 * 4)

__device__ __forceinline__ float dot16(const float4& a0, const float4& a1,
                                       const float4& a2, const float4& a3,
                                       const float4& p0, const float4& p1,
                                       const float4& p2, const float4& p3)
{
    float s = a0.x * p0.x + a0.y * p0.y + a0.z * p0.z + a0.w * p0.w
            + a1.x * p1.x + a1.y * p1.y + a1.z * p1.z + a1.w * p1.w
            + a2.x * p2.x + a2.y * p2.y + a2.z * p2.z + a2.w * p2.w
            + a3.x * p3.x + a3.y * p3.y + a3.z * p3.z + a3.w * p3.w;
#pragma unroll
    for (int o = 16; o; o >>= 1) s += __shfl_xor_sync(0xffffffffu, s, o);
    return s;
}
__device__ __forceinline__ float4 h4_to_f4(uint2 r) {
    const __half2* hp = reinterpret_cast<const __half2*>(&r);
    float2 a = __half22float2(hp[0]), b = __half22float2(hp[1]);
    return make_float4(a.x, a.y, b.x, b.y);
}

__global__ __launch_bounds__(512)
void k_loss(const int* __restrict__ walks, const int* __restrict__ negs)
{
    extern __shared__ char smraw[];
    float4* sm4   = (float4*)smraw;
    int*    ids_s = (int*)(smraw + SMEM_EMB_F4 * 16);
    float*  inv_s = (float*)(smraw + SMEM_EMB_F4 * 16 + WALK_LEN * 4);
    float*  wsum  = (float*)(smraw + SMEM_EMB_F4 * 16 + WALK_LEN * 8);

    int b = blockIdx.x;
    int tid = threadIdx.x, lane = tid & 31, w = tid >> 5;

    if (tid < WALK_LEN) {
        int id = walks[b * WALK_LEN + tid];
        ids_s[tid] = id;
        inv_s[tid] = g_inv[id];
    }
    __syncthreads();

    for (int f = tid; f < WALK_LEN * 64; f += 512) {
        int r = f >> 6, q = f & 63;
        int id = ids_s[r];
        float iv = inv_s[r];
        uint4 raw = (q < 32) ? *(const uint4*)(g_e1h + (size_t)id * 256 + q * 8)
                             : *(const uint4*)(g_e2h + (size_t)id * 256 + (q - 32) * 8);
        float fv[8]; h8_to_f8(raw, fv);
        sm4[r * 128 + 2 * q]     = make_float4(fv[0] * iv, fv[1] * iv, fv[2] * iv, fv[3] * iv);
        sm4[r * 128 + 2 * q + 1] = make_float4(fv[4] * iv, fv[5] * iv, fv[6] * iv, fv[7] * iv);
    }
    __syncthreads();

    float term_acc = 0.f;
    for (int k = 0; k < 4; k++) {
        int l = (w << 2) | k;
        const float4* ar = sm4 + (size_t)l * 128;
        float4 A0 = ar[lane], A1 = ar[32 + lane], A2 = ar[64 + lane], A3 = ar[96 + lane];

        int posid[2 * WINDOW];
        bool pval[2 * WINDOW];
        float pos_sum = 0.f;
#pragma unroll
        for (int p = 0; p < 2 * WINDOW; p++) {
            int off = (p < WINDOW) ? (p - WINDOW) : (p - WINDOW + 1);
            int pp = l + off;
            bool val = (pp >= 0) && (pp < WALK_LEN);
            int ppc = min(max(pp, 0), WALK_LEN - 1);
            pval[p] = val;
            posid[p] = ids_s[ppc];
            const float4* pr = sm4 + (size_t)ppc * 128;
            float4 P0 = pr[lane], P1 = pr[32 + lane], P2 = pr[64 + lane], P3 = pr[96 + lane];
            float d = dot16(A0, A1, A2, A3, P0, P1, P2, P3);
            if (val) pos_sum += __expf(d * INV_TEMP);
        }

        int nbase = (b * WALK_LEN + l) * NEG_S;
        int ngl = (lane < NEG_S) ? negs[nbase + lane] : 0;
        float neg_sum = 0.f;
#pragma unroll
        for (int s = 0; s < NEG_S; s++) {
            int ng = __shfl_sync(0xffffffffu, ngl, s);
            bool inpos = false;
#pragma unroll
            for (int p = 0; p < 2 * WINDOW; p++)
                inpos = inpos || (pval[p] && (ng == posid[p]));
            const __half* n1 = g_e1h + (size_t)ng * 256;
            const __half* n2 = g_e2h + (size_t)ng * 256;
            float4 P0 = h4_to_f4(*(const uint2*)(n1 + 4 * lane));
            float4 P1 = h4_to_f4(*(const uint2*)(n1 + 128 + 4 * lane));
            float4 P2 = h4_to_f4(*(const uint2*)(n2 + 4 * lane));
            float4 P3 = h4_to_f4(*(const uint2*)(n2 + 128 + 4 * lane));
            float d = dot16(A0, A1, A2, A3, P0, P1, P2, P3);
            float sim = d * g_inv[ng] * INV_TEMP;
            if (!inpos) neg_sum += __expf(sim);
        }
        term_acc += log1pf(neg_sum / pos_sum);
    }

    if (lane == 0) wsum[w] = term_acc;
    __syncthreads();
    if (w == 0) {
        float s = (lane < 16) ? wsum[lane] : 0.f;
#pragma unroll
        for (int o = 16; o; o >>= 1) s += __shfl_xor_sync(0xffffffffu, s, o);
        if (lane == 0) g_terms[b] = s;
    }
}

__global__ void k_reduce(float* __restrict__ out)
{
    __shared__ float sh[512];
    int tid = threadIdx.x;
    sh[tid] = (tid < NUM_WALKS) ? g_terms[tid] : 0.f;
    __syncthreads();
    for (int o = 256; o; o >>= 1) {
        if (tid < o) sh[tid] += sh[tid + o];
        __syncthreads();
    }
    if (tid == 0) out[0] = sh[0];
}

// ---------------- driver ---------------------------------------------------
extern "C" void kernel_launch(void* const* d_in, const int* in_sizes, int n_in,
                              void* d_out, int out_size)
{
    const float* x          = (const float*)d_in[0];
    const int*   edge_index = (const int*)  d_in[1];
    const int*   walks      = (const int*)  d_in[2];
    const int*   negs       = (const int*)  d_in[3];
    const float* W1         = (const float*)d_in[4];
    const float* a_src1     = (const float*)d_in[5];
    const float* a_dst1     = (const float*)d_in[6];
    const float* b1         = (const float*)d_in[7];
    const float* W2         = (const float*)d_in[8];
    const float* a_src2     = (const float*)d_in[9];
    const float* a_dst2     = (const float*)d_in[10];
    const float* b2         = (const float*)d_in[11];
    float* out = (float*)d_out;

    float *als1, *ald1, *als2, *ald2, *ss1, *ss2, *alpS, *alpD;
    __half *xw1h, *xw2h, *e1h, *e2h;
    __nv_bfloat16 *a1h, *a1l, *a2h, *a2l, *bw1h, *bw1l, *bw2h, *bw2l;
    void* degp;
    cudaGetSymbolAddress((void**)&xw1h, g_xw1h);
    cudaGetSymbolAddress((void**)&xw2h, g_xw2h);
    cudaGetSymbolAddress((void**)&e1h,  g_e1h);
    cudaGetSymbolAddress((void**)&e2h,  g_e2h);
    cudaGetSymbolAddress((void**)&als1, g_als1);
    cudaGetSymbolAddress((void**)&ald1, g_ald1);
    cudaGetSymbolAddress((void**)&als2, g_als2);
    cudaGetSymbolAddress((void**)&ald2, g_ald2);
    cudaGetSymbolAddress((void**)&alpS, g_alpS);
    cudaGetSymbolAddress((void**)&alpD, g_alpD);
    cudaGetSymbolAddress((void**)&ss1,  g_ss1);
    cudaGetSymbolAddress((void**)&ss2,  g_ss2);
    cudaGetSymbolAddress((void**)&a1h,  g_a1h);
    cudaGetSymbolAddress((void**)&a1l,  g_a1l);
    cudaGetSymbolAddress((void**)&a2h,  g_a2h);
    cudaGetSymbolAddress((void**)&a2l,  g_a2l);
    cudaGetSymbolAddress((void**)&bw1h, g_b1h);
    cudaGetSymbolAddress((void**)&bw1l, g_b1l);
    cudaGetSymbolAddress((void**)&bw2h, g_b2h);
    cudaGetSymbolAddress((void**)&bw2l, g_b2l);
    cudaGetSymbolAddress(&degp, g_deg);

    static int attr_set = 0;
    if (!attr_set) {
        cudaFuncSetAttribute(k_loss, cudaFuncAttributeMaxDynamicSharedMemorySize,
                             SMEM_LOSS_BYTES);
        cudaFuncSetAttribute(k_mmagemm<1>, cudaFuncAttributeMaxDynamicSharedMemorySize,
                             MSM_TOTAL);
        cudaFuncSetAttribute(k_mmagemm<2>, cudaFuncAttributeMaxDynamicSharedMemorySize,
                             MSM_TOTAL);
        attr_set = 1;
    }

    // CSR build
    cudaMemsetAsync(degp, 0, NN * sizeof(int));
    k_count<<<(EE + 255) / 256, 256>>>(edge_index);
    k_scan<<<1, 1024>>>();
    k_scatter<<<(EE + 255) / 256, 256>>>(edge_index);

    // operand conversions
    k_split_x<<<(NPAD * FIN / 4 + 255) / 256, 256>>>(x);
    k_split_w<<<(256 * FIN + 255) / 256, 256>>>(W1, bw1h, bw1l, FIN);
    k_split_w<<<(256 * H1 + 255) / 256, 256>>>(W2, bw2h, bw2l, H1);

    // layer 1 (al folded into GEMM epilogue)
    k_mmagemm<1><<<dim3(NPAD / 128, 2), 256, MSM_TOTAL>>>(
        a1h, a1l, bw1h, bw1l, xw1h, FIN, a_src1, a_dst1, als1, ald1);
    k_agg_w<NHEADS, true, true><<<(NN * 32 + 255) / 256, 256>>>(
        xw1h, als1, ald1, b1, e1h, ss1, a2h, a2l);

    // layer 2
    k_mmagemm<2><<<dim3(NPAD / 128, 2), 256, MSM_TOTAL>>>(
        a2h, a2l, bw2h, bw2l, xw2h, H1, a_src2, a_dst2, alpS, alpD);
    k_alsum2<<<(NN + 255) / 256, 256>>>();
    k_agg_w<1, false, false><<<(NN * 32 + 255) / 256, 256>>>(
        xw2h, als2, ald2, b2, e2h, ss2, nullptr, nullptr);

    // loss
    k_inv<<<(NN + 255) / 256, 256>>>();
    k_loss<<<NUM_WALKS, 512, SMEM_LOSS_BYTES>>>(walks, negs);
    k_reduce<<<1, 512>>>(out);
}

// round 8
// speedup vs baseline: 2.6786x; 1.1202x over previous
#include <cuda_runtime.h>
#include <cuda_bf16.h>
#include <cuda_fp16.h>
#include <cstdint>

#define NN 50000
#define NPAD 50048
#define EE 800000
#define FIN 128
#define HID 32
#define NHEADS 8
#define H1 256
#define NUM_WALKS 512
#define WALK_LEN 64
#define WINDOW 5
#define NEG_S 10
#define NEG_SLOPE 0.2f
#define INV_TEMP (1.0f/0.07f)

// ---------------- scratch (device globals; no cudaMalloc allowed) ----------
__device__ __half g_xw1h[(size_t)NPAD * H1];
__device__ __half g_xw2h[(size_t)NPAD * H1];
__device__ __half g_e1h[(size_t)NN * H1];
__device__ __half g_e2h[(size_t)NN * H1];
__device__ float g_als1[(size_t)NPAD * NHEADS];
__device__ float g_ald1[(size_t)NPAD * NHEADS];
__device__ float g_als2[NN];
__device__ float g_ald2[NN];
__device__ float g_alpS[8 * NPAD];
__device__ float g_alpD[8 * NPAD];
__device__ float g_ss1[NN];
__device__ float g_inv[NN];
__device__ int   g_deg[NN];
__device__ int   g_rowptr[NN + 1];
__device__ int   g_wptr[NN];
__device__ int   g_col[EE];
__device__ float g_terms[NUM_WALKS];
__device__ __nv_bfloat16 g_a1h[(size_t)NPAD * FIN];
__device__ __nv_bfloat16 g_a1l[(size_t)NPAD * FIN];
__device__ __nv_bfloat16 g_a2h[(size_t)NPAD * H1];
__device__ __nv_bfloat16 g_a2l[(size_t)NPAD * H1];
__device__ __nv_bfloat16 g_b1h[256 * FIN];
__device__ __nv_bfloat16 g_b1l[256 * FIN];
__device__ __nv_bfloat16 g_b2h[256 * H1];
__device__ __nv_bfloat16 g_b2l[256 * H1];

// ---------------- PTX helpers (arch-generic sm_80+) ------------------------
__device__ __forceinline__ uint32_t smem_u32(const void* p) {
    uint32_t a;
    asm("{ .reg .u64 t; cvta.to.shared.u64 t, %1; cvt.u32.u64 %0, t; }" : "=r"(a) : "l"(p));
    return a;
}
#define CP16(SADDR, GPTR) \
    asm volatile("cp.async.cg.shared.global [%0], [%1], 16;" :: "r"(SADDR), "l"(GPTR))
#define CP_COMMIT() asm volatile("cp.async.commit_group;" ::: "memory")
#define CP_WAIT(N)  asm volatile("cp.async.wait_group %0;" :: "n"(N) : "memory")
#define LDSM4(R, ADDR) \
    asm volatile("ldmatrix.sync.aligned.m8n8.x4.shared.b16 {%0,%1,%2,%3}, [%4];" \
        : "=r"((R)[0]), "=r"((R)[1]), "=r"((R)[2]), "=r"((R)[3]) : "r"(ADDR))
#define MMA16816(C, A, B0, B1) \
    asm volatile("mma.sync.aligned.m16n8k16.row.col.f32.bf16.bf16.f32 " \
        "{%0,%1,%2,%3}, {%4,%5,%6,%7}, {%8,%9}, {%0,%1,%2,%3};" \
        : "+f"((C)[0]), "+f"((C)[1]), "+f"((C)[2]), "+f"((C)[3]) \
        : "r"((A)[0]), "r"((A)[1]), "r"((A)[2]), "r"((A)[3]), "r"(B0), "r"(B1))

__device__ __forceinline__ unsigned pk_bf2(float a, float b) {
    __nv_bfloat162 t;
    t.x = __float2bfloat16_rn(a);
    t.y = __float2bfloat16_rn(b);
    return *reinterpret_cast<unsigned*>(&t);
}
__device__ __forceinline__ void h8_to_f8(const uint4& r, float* f) {
    const __half2* hp = reinterpret_cast<const __half2*>(&r);
#pragma unroll
    for (int i = 0; i < 4; i++) {
        float2 t = __half22float2(hp[i]);
        f[2 * i] = t.x; f[2 * i + 1] = t.y;
    }
}

// ---------------- CSR build ------------------------------------------------
__global__ void k_count(const int* __restrict__ edge_index) {
    int e = blockIdx.x * blockDim.x + threadIdx.x;
    if (e < EE) atomicAdd(&g_deg[edge_index[EE + e]], 1);
}

__global__ void k_scan() {
    __shared__ int wsums[32];
    __shared__ int carry_s;
    int tid = threadIdx.x, lane = tid & 31, w = tid >> 5;
    if (tid == 0) carry_s = 0;
    __syncthreads();
    for (int base = 0; base < NN; base += 4096) {
        int i0 = base + tid * 4;
        int v[4];
        if (i0 + 4 <= NN) {
            int4 q = *(const int4*)(g_deg + i0);
            v[0] = q.x; v[1] = q.y; v[2] = q.z; v[3] = q.w;
        } else {
#pragma unroll
            for (int j = 0; j < 4; j++) v[j] = (i0 + j < NN) ? g_deg[i0 + j] : 0;
        }
        int tsum = v[0] + v[1] + v[2] + v[3];
        int inc = tsum;
#pragma unroll
        for (int o = 1; o < 32; o <<= 1) {
            int t = __shfl_up_sync(0xffffffffu, inc, o);
            if (lane >= o) inc += t;
        }
        if (lane == 31) wsums[w] = inc;
        __syncthreads();
        if (w == 0) {
            int ws = wsums[lane];
#pragma unroll
            for (int o = 1; o < 32; o <<= 1) {
                int t = __shfl_up_sync(0xffffffffu, ws, o);
                if (lane >= o) ws += t;
            }
            wsums[lane] = ws;
        }
        __syncthreads();
        int offset = carry_s + (w ? wsums[w - 1] : 0) + inc - tsum;
        int e0 = offset, e1 = e0 + v[0], e2 = e1 + v[1], e3 = e2 + v[2];
        if (i0 < NN)     { g_rowptr[i0]     = e0; g_wptr[i0]     = e0; }
        if (i0 + 1 < NN) { g_rowptr[i0 + 1] = e1; g_wptr[i0 + 1] = e1; }
        if (i0 + 2 < NN) { g_rowptr[i0 + 2] = e2; g_wptr[i0 + 2] = e2; }
        if (i0 + 3 < NN) { g_rowptr[i0 + 3] = e3; g_wptr[i0 + 3] = e3; }
        __syncthreads();
        if (tid == 1023) carry_s = offset + tsum;
        __syncthreads();
    }
    if (tid == 0) g_rowptr[NN] = carry_s;
}

__global__ void k_scatter(const int* __restrict__ edge_index) {
    int e = blockIdx.x * blockDim.x + threadIdx.x;
    if (e < EE) {
        int src = edge_index[e];
        int dst = edge_index[EE + e];
        g_col[atomicAdd(&g_wptr[dst], 1)] = src;
    }
}

// ---------------- bf16 split conversions -----------------------------------
__global__ void k_split_x(const float* __restrict__ x) {
    int t = blockIdx.x * blockDim.x + threadIdx.x;
    if (t >= NPAD * FIN / 4) return;
    int base = t * 4;
    int row = base >> 7;
    float4 v = (row < NN) ? *(const float4*)(x + base) : make_float4(0.f, 0.f, 0.f, 0.f);
    float a[4] = {v.x, v.y, v.z, v.w};
    float l[4];
#pragma unroll
    for (int i = 0; i < 4; i++)
        l[i] = a[i] - __bfloat162float(__float2bfloat16_rn(a[i]));
    *(uint2*)(g_a1h + base) = make_uint2(pk_bf2(a[0], a[1]), pk_bf2(a[2], a[3]));
    *(uint2*)(g_a1l + base) = make_uint2(pk_bf2(l[0], l[1]), pk_bf2(l[2], l[3]));
}

__global__ void k_split_wboth(const float* __restrict__ W1f, const float* __restrict__ W2f) {
    int t = blockIdx.x * blockDim.x + threadIdx.x;
    if (t < 256 * FIN) {
        int n = t / FIN, k = t - n * FIN;
        float v = W1f[k * 256 + n];
        __nv_bfloat16 hb = __float2bfloat16_rn(v);
        g_b1h[t] = hb;
        g_b1l[t] = __float2bfloat16_rn(v - __bfloat162float(hb));
    } else if (t < 256 * FIN + 256 * H1) {
        int u = t - 256 * FIN;
        int n = u / H1, k = u - n * H1;
        float v = W2f[k * 256 + n];
        __nv_bfloat16 hb = __float2bfloat16_rn(v);
        g_b2h[u] = hb;
        g_b2l[u] = __float2bfloat16_rn(v - __bfloat162float(hb));
    }
}

// ---------------- HMMA split-bf16 GEMM, fp16 C, fused al epilogue ----------
#define MBUF 10240
#define MSTAGE (4 * MBUF)
#define MSM_TOTAL (2 * MSTAGE)

__device__ __forceinline__ void stage_chunk(
    uint32_t sb32, int rbase, int nbase, int k0, int K, int tid,
    const __nv_bfloat16* __restrict__ Ah, const __nv_bfloat16* __restrict__ Al,
    const __nv_bfloat16* __restrict__ Bh, const __nv_bfloat16* __restrict__ Bl)
{
#pragma unroll
    for (int t = tid; t < 512; t += 256) {
        int r = t >> 2, seg = t & 3;
        uint32_t so = sb32 + r * 80 + seg * 16;
        size_t ga = (size_t)(rbase + r) * K + k0 + seg * 8;
        size_t gb = (size_t)(nbase + r) * K + k0 + seg * 8;
        CP16(so,             Ah + ga);
        CP16(so + MBUF,      Al + ga);
        CP16(so + 2 * MBUF,  Bh + gb);
        CP16(so + 3 * MBUF,  Bl + gb);
    }
}

template<int FOLD>
__global__ __launch_bounds__(256)
void k_mmagemm(const __nv_bfloat16* __restrict__ Ah, const __nv_bfloat16* __restrict__ Al,
               const __nv_bfloat16* __restrict__ Bh, const __nv_bfloat16* __restrict__ Bl,
               __half* __restrict__ C, int K,
               const float* __restrict__ avs, const float* __restrict__ avd,
               float* __restrict__ foldS, float* __restrict__ foldD)
{
    extern __shared__ char sm[];
    uint32_t smb = smem_u32(sm);
    int tid = threadIdx.x, lane = tid & 31, wid = tid >> 5;
    int rbase = blockIdx.x * 128, nbase = blockIdx.y * 128;
    int wm = (wid >> 2) * 64, wn = (wid & 3) * 32;

    float acc[4][4][4];
#pragma unroll
    for (int i = 0; i < 4; i++)
#pragma unroll
        for (int j = 0; j < 4; j++)
#pragma unroll
            for (int q = 0; q < 4; q++) acc[i][j][q] = 0.f;

    int nch = K >> 5;
    stage_chunk(smb, rbase, nbase, 0, K, tid, Ah, Al, Bh, Bl);
    CP_COMMIT();

    int row = lane & 15, kh = lane >> 4;
    for (int ch = 0; ch < nch; ch++) {
        if (ch + 1 < nch) {
            stage_chunk(smb + ((ch + 1) & 1) * MSTAGE, rbase, nbase, (ch + 1) << 5, K, tid,
                        Ah, Al, Bh, Bl);
            CP_COMMIT();
            CP_WAIT(1);
        } else {
            CP_WAIT(0);
        }
        __syncthreads();

        uint32_t s0 = smb + (ch & 1) * MSTAGE;
#pragma unroll
        for (int s = 0; s < 2; s++) {
            int colb = (s * 16 + kh * 8) * 2;
            uint32_t ah[4][4], al[4][4], bh[2][4], bl[2][4];
#pragma unroll
            for (int mi = 0; mi < 4; mi++) {
                uint32_t ad = s0 + (wm + mi * 16 + row) * 80 + colb;
                LDSM4(ah[mi], ad);
                LDSM4(al[mi], ad + MBUF);
            }
#pragma unroll
            for (int bi = 0; bi < 2; bi++) {
                uint32_t ad = s0 + 2 * MBUF + (wn + bi * 16 + row) * 80 + colb;
                LDSM4(bh[bi], ad);
                LDSM4(bl[bi], ad + MBUF);
            }
#pragma unroll
            for (int mi = 0; mi < 4; mi++)
#pragma unroll
                for (int ni = 0; ni < 4; ni++) {
                    int bi = ni >> 1, hf = ni & 1;
                    MMA16816(acc[mi][ni], ah[mi], bh[bi][hf], bh[bi][hf + 2]);
                    MMA16816(acc[mi][ni], ah[mi], bl[bi][hf], bl[bi][hf + 2]);
                    MMA16816(acc[mi][ni], al[mi], bh[bi][hf], bh[bi][hf + 2]);
                }
        }
        __syncthreads();
    }

#pragma unroll
    for (int mi = 0; mi < 4; mi++)
#pragma unroll
        for (int ni = 0; ni < 4; ni++) {
            int r0 = rbase + wm + mi * 16 + (lane >> 2);
            int c  = nbase + wn + ni * 8 + (lane & 3) * 2;
            __half* p = C + (size_t)r0 * 256 + c;
            *(__half2*)p = __floats2half2_rn(acc[mi][ni][0], acc[mi][ni][1]);
            *(__half2*)(p + 8 * 256) = __floats2half2_rn(acc[mi][ni][2], acc[mi][ni][3]);
        }

    // fused attention-logit fold
    {
        int h = (nbase + wn) >> 5;
        int slot = blockIdx.y * 4 + (wid & 3);
#pragma unroll
        for (int mi = 0; mi < 4; mi++) {
            float ps0 = 0.f, ps1 = 0.f, pd0 = 0.f, pd1 = 0.f;
#pragma unroll
            for (int ni = 0; ni < 4; ni++) {
                int cc = ni * 8 + (lane & 3) * 2;
                float s0, s1, d0, d1;
                if (FOLD == 1) {
                    s0 = avs[h * 32 + cc]; s1 = avs[h * 32 + cc + 1];
                    d0 = avd[h * 32 + cc]; d1 = avd[h * 32 + cc + 1];
                } else {
                    int c = nbase + wn + cc;
                    s0 = avs[c]; s1 = avs[c + 1];
                    d0 = avd[c]; d1 = avd[c + 1];
                }
                ps0 += acc[mi][ni][0] * s0 + acc[mi][ni][1] * s1;
                ps1 += acc[mi][ni][2] * s0 + acc[mi][ni][3] * s1;
                pd0 += acc[mi][ni][0] * d0 + acc[mi][ni][1] * d1;
                pd1 += acc[mi][ni][2] * d0 + acc[mi][ni][3] * d1;
            }
#pragma unroll
            for (int o = 1; o <= 2; o <<= 1) {
                ps0 += __shfl_xor_sync(0xffffffffu, ps0, o);
                ps1 += __shfl_xor_sync(0xffffffffu, ps1, o);
                pd0 += __shfl_xor_sync(0xffffffffu, pd0, o);
                pd1 += __shfl_xor_sync(0xffffffffu, pd1, o);
            }
            if ((lane & 3) == 0) {
                int r0 = rbase + wm + mi * 16 + (lane >> 2);
                if (FOLD == 1) {
                    foldS[(size_t)r0 * 8 + h] = ps0;
                    foldS[(size_t)(r0 + 8) * 8 + h] = ps1;
                    foldD[(size_t)r0 * 8 + h] = pd0;
                    foldD[(size_t)(r0 + 8) * 8 + h] = pd1;
                } else {
                    foldS[(size_t)slot * NPAD + r0] = ps0;
                    foldS[(size_t)slot * NPAD + r0 + 8] = ps1;
                    foldD[(size_t)slot * NPAD + r0] = pd0;
                    foldD[(size_t)slot * NPAD + r0 + 8] = pd1;
                }
            }
        }
    }
}

// sum the 8 layer-2 al partial slots (deterministic)
__global__ void k_alsum2()
{
    int i = blockIdx.x * blockDim.x + threadIdx.x;
    if (i >= NN) return;
    float s = 0.f, d = 0.f;
#pragma unroll
    for (int k = 0; k < 8; k++) {
        s += g_alpS[(size_t)k * NPAD + i];
        d += g_alpD[(size_t)k * NPAD + i];
    }
    g_als2[i] = s;
    g_ald2[i] = d;
}

// ---------------- warp-per-node softmax aggregation (fp16 gather) ----------
// FININV: layer-2 mode — write g_inv from ss1 + own ssq instead of ssout.
template<int H, bool ELU, bool SPLIT, bool FININV>
__global__ __launch_bounds__(256)
void k_agg_w(const __half* __restrict__ xw, const float* __restrict__ als,
             const float* __restrict__ ald, const float* __restrict__ bias,
             __half* __restrict__ outh, float* __restrict__ ssout,
             __nv_bfloat16* __restrict__ sph, __nv_bfloat16* __restrict__ spl)
{
    int gw = (blockIdx.x * blockDim.x + threadIdx.x) >> 5;
    int lane = threadIdx.x & 31;
    if (gw >= NN) return;
    int n = gw;
    int beg = g_rowptr[n];
    int deg = g_rowptr[n + 1] - beg;

    const int myh = (lane * H) >> 5;
    const float admy = ald[(size_t)n * H + myh];

    float eself = als[(size_t)n * H + myh] + admy;
    eself = eself > 0.f ? eself : NEG_SLOPE * eself;
    float exs = __expf(eself);
    float den = exs;

    float acc[8];
    {
        uint4 raw = *(const uint4*)(xw + (size_t)n * 256 + (lane << 3));
        float f[8]; h8_to_f8(raw, f);
#pragma unroll
        for (int t = 0; t < 8; t++) acc[t] = exs * f[t];
    }

    for (int base = 0; base < deg; base += 32) {
        int idx = base + lane;
        int scol = (idx < deg) ? g_col[beg + idx] : 0;
        int cn = min(32, deg - base);
#pragma unroll 4
        for (int jj = 0; jj < cn; jj++) {
            int s = __shfl_sync(0xffffffffu, scol, jj);
            float e = als[(size_t)s * H + myh] + admy;
            e = e > 0.f ? e : NEG_SLOPE * e;
            float ex = __expf(e);
            den += ex;
            uint4 raw = *(const uint4*)(xw + (size_t)s * 256 + (lane << 3));
            float f[8]; h8_to_f8(raw, f);
#pragma unroll
            for (int t = 0; t < 8; t++) acc[t] += ex * f[t];
        }
    }

    float invd = 1.f / den;
    const float4* bb = (const float4*)(bias + (lane << 3));
    float4 b0 = bb[0], b1 = bb[1];
    float o[8];
    o[0] = acc[0] * invd + b0.x; o[1] = acc[1] * invd + b0.y;
    o[2] = acc[2] * invd + b0.z; o[3] = acc[3] * invd + b0.w;
    o[4] = acc[4] * invd + b1.x; o[5] = acc[5] * invd + b1.y;
    o[6] = acc[6] * invd + b1.z; o[7] = acc[7] * invd + b1.w;
    float ssq = 0.f;
#pragma unroll
    for (int t = 0; t < 8; t++) {
        if (ELU) o[t] = o[t] > 0.f ? o[t] : expm1f(o[t]);
        ssq += o[t] * o[t];
    }
    {
        uint4 ho;
        __half2* hp = (__half2*)&ho;
        hp[0] = __floats2half2_rn(o[0], o[1]);
        hp[1] = __floats2half2_rn(o[2], o[3]);
        hp[2] = __floats2half2_rn(o[4], o[5]);
        hp[3] = __floats2half2_rn(o[6], o[7]);
        *(uint4*)(outh + (size_t)n * 256 + (lane << 3)) = ho;
    }
    if (SPLIT) {
        unsigned hh[4], ll[4];
#pragma unroll
        for (int t2 = 0; t2 < 4; t2++) {
            float a = o[2 * t2], b = o[2 * t2 + 1];
            float la = a - __bfloat162float(__float2bfloat16_rn(a));
            float lb = b - __bfloat162float(__float2bfloat16_rn(b));
            hh[t2] = pk_bf2(a, b);
            ll[t2] = pk_bf2(la, lb);
        }
        *(uint4*)(sph + (size_t)n * 256 + (lane << 3)) = make_uint4(hh[0], hh[1], hh[2], hh[3]);
        *(uint4*)(spl + (size_t)n * 256 + (lane << 3)) = make_uint4(ll[0], ll[1], ll[2], ll[3]);
    }
#pragma unroll
    for (int oo = 16; oo; oo >>= 1) ssq += __shfl_xor_sync(0xffffffffu, ssq, oo);
    if (lane == 0) {
        if (FININV) g_inv[n] = 1.f / fmaxf(sqrtf(ssout[n] + ssq), 1e-8f);
        else        ssout[n] = ssq;
    }
}

// ---------------- contrastive loss: block per walk, fp16 gathers -----------
#define SMEM_EMB_F4 (WALK_LEN * 128)
#define SMEM_LOSS_BYTES (SMEM_EMB_F4 * 16 + WALK_LEN * 4 + WALK_LEN * 4 + 16 * 4)

__device__ __forceinline__ float dot16(const float4& a0, const float4& a1,
                                       const float4& a2, const float4& a3,
                                       const float4& p0, const float4& p1,
                                       const float4& p2, const float4& p3)
{
    float s = a0.x * p0.x + a0.y * p0.y + a0.z * p0.z + a0.w * p0.w
            + a1.x * p1.x + a1.y * p1.y + a1.z * p1.z + a1.w * p1.w
            + a2.x * p2.x + a2.y * p2.y + a2.z * p2.z + a2.w * p2.w
            + a3.x * p3.x + a3.y * p3.y + a3.z * p3.z + a3.w * p3.w;
#pragma unroll
    for (int o = 16; o; o >>= 1) s += __shfl_xor_sync(0xffffffffu, s, o);
    return s;
}
__device__ __forceinline__ float4 h4_to_f4(uint2 r) {
    const __half2* hp = reinterpret_cast<const __half2*>(&r);
    float2 a = __half22float2(hp[0]), b = __half22float2(hp[1]);
    return make_float4(a.x, a.y, b.x, b.y);
}

__global__ __launch_bounds__(512)
void k_loss(const int* __restrict__ walks, const int* __restrict__ negs)
{
    extern __shared__ char smraw[];
    float4* sm4   = (float4*)smraw;
    int*    ids_s = (int*)(smraw + SMEM_EMB_F4 * 16);
    float*  inv_s = (float*)(smraw + SMEM_EMB_F4 * 16 + WALK_LEN * 4);
    float*  wsum  = (float*)(smraw + SMEM_EMB_F4 * 16 + WALK_LEN * 8);

    int b = blockIdx.x;
    int tid = threadIdx.x, lane = tid & 31, w = tid >> 5;

    if (tid < WALK_LEN) {
        int id = walks[b * WALK_LEN + tid];
        ids_s[tid] = id;
        inv_s[tid] = g_inv[id];
    }
    __syncthreads();

    for (int f = tid; f < WALK_LEN * 64; f += 512) {
        int r = f >> 6, q = f & 63;
        int id = ids_s[r];
        float iv = inv_s[r];
        uint4 raw = (q < 32) ? *(const uint4*)(g_e1h + (size_t)id * 256 + q * 8)
                             : *(const uint4*)(g_e2h + (size_t)id * 256 + (q - 32) * 8);
        float fv[8]; h8_to_f8(raw, fv);
        sm4[r * 128 + 2 * q]     = make_float4(fv[0] * iv, fv[1] * iv, fv[2] * iv, fv[3] * iv);
        sm4[r * 128 + 2 * q + 1] = make_float4(fv[4] * iv, fv[5] * iv, fv[6] * iv, fv[7] * iv);
    }
    __syncthreads();

    float term_acc = 0.f;
    for (int k = 0; k < 4; k++) {
        int l = (w << 2) | k;
        const float4* ar = sm4 + (size_t)l * 128;
        float4 A0 = ar[lane], A1 = ar[32 + lane], A2 = ar[64 + lane], A3 = ar[96 + lane];

        int posid[2 * WINDOW];
        bool pval[2 * WINDOW];
        float pos_sum = 0.f;
#pragma unroll
        for (int p = 0; p < 2 * WINDOW; p++) {
            int off = (p < WINDOW) ? (p - WINDOW) : (p - WINDOW + 1);
            int pp = l + off;
            bool val = (pp >= 0) && (pp < WALK_LEN);
            int ppc = min(max(pp, 0), WALK_LEN - 1);
            pval[p] = val;
            posid[p] = ids_s[ppc];
            const float4* pr = sm4 + (size_t)ppc * 128;
            float4 P0 = pr[lane], P1 = pr[32 + lane], P2 = pr[64 + lane], P3 = pr[96 + lane];
            float d = dot16(A0, A1, A2, A3, P0, P1, P2, P3);
            if (val) pos_sum += __expf(d * INV_TEMP);
        }

        int nbase = (b * WALK_LEN + l) * NEG_S;
        int ngl = (lane < NEG_S) ? negs[nbase + lane] : 0;
        float neg_sum = 0.f;
#pragma unroll
        for (int s = 0; s < NEG_S; s++) {
            int ng = __shfl_sync(0xffffffffu, ngl, s);
            bool inpos = false;
#pragma unroll
            for (int p = 0; p < 2 * WINDOW; p++)
                inpos = inpos || (pval[p] && (ng == posid[p]));
            const __half* n1 = g_e1h + (size_t)ng * 256;
            const __half* n2 = g_e2h + (size_t)ng * 256;
            float4 P0 = h4_to_f4(*(const uint2*)(n1 + 4 * lane));
            float4 P1 = h4_to_f4(*(const uint2*)(n1 + 128 + 4 * lane));
            float4 P2 = h4_to_f4(*(const uint2*)(n2 + 4 * lane));
            float4 P3 = h4_to_f4(*(const uint2*)(n2 + 128 + 4 * lane));
            float d = dot16(A0, A1, A2, A3, P0, P1, P2, P3);
            float sim = d * g_inv[ng] * INV_TEMP;
            if (!inpos) neg_sum += __expf(sim);
        }
        term_acc += log1pf(neg_sum / pos_sum);
    }

    if (lane == 0) wsum[w] = term_acc;
    __syncthreads();
    if (w == 0) {
        float s = (lane < 16) ? wsum[lane] : 0.f;
#pragma unroll
        for (int o = 16; o; o >>= 1) s += __shfl_xor_sync(0xffffffffu, s, o);
        if (lane == 0) g_terms[b] = s;
    }
}

__global__ void k_reduce(float* __restrict__ out)
{
    __shared__ float sh[512];
    int tid = threadIdx.x;
    sh[tid] = (tid < NUM_WALKS) ? g_terms[tid] : 0.f;
    __syncthreads();
    for (int o = 256; o; o >>= 1) {
        if (tid < o) sh[tid] += sh[tid + o];
        __syncthreads();
    }
    if (tid == 0) out[0] = sh[0];
}

// ---------------- driver ---------------------------------------------------
extern "C" void kernel_launch(void* const* d_in, const int* in_sizes, int n_in,
                              void* d_out, int out_size)
{
    const float* x          = (const float*)d_in[0];
    const int*   edge_index = (const int*)  d_in[1];
    const int*   walks      = (const int*)  d_in[2];
    const int*   negs       = (const int*)  d_in[3];
    const float* W1         = (const float*)d_in[4];
    const float* a_src1     = (const float*)d_in[5];
    const float* a_dst1     = (const float*)d_in[6];
    const float* b1         = (const float*)d_in[7];
    const float* W2         = (const float*)d_in[8];
    const float* a_src2     = (const float*)d_in[9];
    const float* a_dst2     = (const float*)d_in[10];
    const float* b2         = (const float*)d_in[11];
    float* out = (float*)d_out;

    float *als1, *ald1, *als2, *ald2, *ss1, *alpS, *alpD;
    __half *xw1h, *xw2h, *e1h, *e2h;
    __nv_bfloat16 *a1h, *a1l, *a2h, *a2l, *bw1h, *bw1l, *bw2h, *bw2l;
    void* degp;
    cudaGetSymbolAddress((void**)&xw1h, g_xw1h);
    cudaGetSymbolAddress((void**)&xw2h, g_xw2h);
    cudaGetSymbolAddress((void**)&e1h,  g_e1h);
    cudaGetSymbolAddress((void**)&e2h,  g_e2h);
    cudaGetSymbolAddress((void**)&als1, g_als1);
    cudaGetSymbolAddress((void**)&ald1, g_ald1);
    cudaGetSymbolAddress((void**)&als2, g_als2);
    cudaGetSymbolAddress((void**)&ald2, g_ald2);
    cudaGetSymbolAddress((void**)&alpS, g_alpS);
    cudaGetSymbolAddress((void**)&alpD, g_alpD);
    cudaGetSymbolAddress((void**)&ss1,  g_ss1);
    cudaGetSymbolAddress((void**)&a1h,  g_a1h);
    cudaGetSymbolAddress((void**)&a1l,  g_a1l);
    cudaGetSymbolAddress((void**)&a2h,  g_a2h);
    cudaGetSymbolAddress((void**)&a2l,  g_a2l);
    cudaGetSymbolAddress((void**)&bw1h, g_b1h);
    cudaGetSymbolAddress((void**)&bw1l, g_b1l);
    cudaGetSymbolAddress((void**)&bw2h, g_b2h);
    cudaGetSymbolAddress((void**)&bw2l, g_b2l);
    cudaGetSymbolAddress(&degp, g_deg);

    static cudaStream_t s2 = nullptr;
    static cudaEvent_t evF = nullptr, evJ = nullptr;
    static int attr_set = 0;
    if (!attr_set) {   // first (uncaptured) correctness call: create resources
        cudaFuncSetAttribute(k_loss, cudaFuncAttributeMaxDynamicSharedMemorySize,
                             SMEM_LOSS_BYTES);
        cudaFuncSetAttribute(k_mmagemm<1>, cudaFuncAttributeMaxDynamicSharedMemorySize,
                             MSM_TOTAL);
        cudaFuncSetAttribute(k_mmagemm<2>, cudaFuncAttributeMaxDynamicSharedMemorySize,
                             MSM_TOTAL);
        cudaStreamCreateWithFlags(&s2, cudaStreamNonBlocking);
        cudaEventCreateWithFlags(&evF, cudaEventDisableTiming);
        cudaEventCreateWithFlags(&evJ, cudaEventDisableTiming);
        attr_set = 1;
    }

    // ---- fork: CSR build on s2, conversions + GEMM1 on main stream --------
    cudaEventRecord(evF, 0);
    cudaStreamWaitEvent(s2, evF, 0);

    cudaMemsetAsync(degp, 0, NN * sizeof(int), s2);
    k_count<<<(EE + 255) / 256, 256, 0, s2>>>(edge_index);
    k_scan<<<1, 1024, 0, s2>>>();
    k_scatter<<<(EE + 255) / 256, 256, 0, s2>>>(edge_index);
    cudaEventRecord(evJ, s2);

    k_split_x<<<(NPAD * FIN / 4 + 255) / 256, 256>>>(x);
    k_split_wboth<<<(256 * (FIN + H1) + 255) / 256, 256>>>(W1, W2);
    k_mmagemm<1><<<dim3(NPAD / 128, 2), 256, MSM_TOTAL>>>(
        a1h, a1l, bw1h, bw1l, xw1h, FIN, a_src1, a_dst1, als1, ald1);

    // ---- join --------------------------------------------------------------
    cudaStreamWaitEvent(0, evJ, 0);

    // layer 1 aggregation
    k_agg_w<NHEADS, true, true, false><<<(NN * 32 + 255) / 256, 256>>>(
        xw1h, als1, ald1, b1, e1h, ss1, a2h, a2l);

    // layer 2
    k_mmagemm<2><<<dim3(NPAD / 128, 2), 256, MSM_TOTAL>>>(
        a2h, a2l, bw2h, bw2l, xw2h, H1, a_src2, a_dst2, alpS, alpD);
    k_alsum2<<<(NN + 255) / 256, 256>>>();
    k_agg_w<1, false, false, true><<<(NN * 32 + 255) / 256, 256>>>(
        xw2h, als2, ald2, b2, e2h, ss1, nullptr, nullptr);

    // loss
    k_loss<<<NUM_WALKS, 512, SMEM_LOSS_BYTES>>>(walks, negs);
    k_reduce<<<1, 512>>>(out);
}

// round 10
// speedup vs baseline: 2.9366x; 1.0963x over previous
#include <cuda_runtime.h>
#include <cuda_fp16.h>
#include <cstdint>

#define NN 50000
#define NPAD 50048
#define EE 800000
#define FIN 128
#define HID 32
#define NHEADS 8
#define H1 256
#define NUM_WALKS 512
#define WALK_LEN 64
#define WINDOW 5
#define NEG_S 10
#define NEG_SLOPE 0.2f
#define INV_TEMP (1.0f/0.07f)

// ---------------- scratch (device globals; no cudaMalloc allowed) ----------
__device__ __half g_xh[(size_t)NPAD * FIN];     // fp16 x (GEMM1 A)
__device__ __half g_w1t[256 * FIN];             // fp16 W1^T [N][K]
__device__ __half g_w2t[256 * H1];              // fp16 W2^T [N][K]
__device__ __half g_xw1h[(size_t)NPAD * H1];
__device__ __half g_xw2h[(size_t)NPAD * H1];
__device__ __half g_e1h[(size_t)NPAD * H1];     // fp16 emb1 (loss + GEMM2 A; pad rows stay 0)
__device__ __half g_e2h[(size_t)NN * H1];
__device__ float g_als1[(size_t)NPAD * NHEADS];
__device__ float g_ald1[(size_t)NPAD * NHEADS];
__device__ float g_als2[NN];
__device__ float g_ald2[NN];
__device__ float g_alpS[8 * NPAD];
__device__ float g_alpD[8 * NPAD];
__device__ float g_ss1[NN];
__device__ float g_inv[NN];
__device__ int   g_deg[NN];
__device__ int   g_rowptr[NN + 1];
__device__ int   g_wptr[NN];
__device__ int   g_col[EE];
__device__ float g_terms[NUM_WALKS];
__device__ unsigned g_done;                     // loss last-block ticket (self-resetting)

// ---------------- PTX helpers (arch-generic sm_80+) ------------------------
__device__ __forceinline__ uint32_t smem_u32(const void* p) {
    uint32_t a;
    asm("{ .reg .u64 t; cvta.to.shared.u64 t, %1; cvt.u32.u64 %0, t; }" : "=r"(a) : "l"(p));
    return a;
}
#define CP16(SADDR, GPTR) \
    asm volatile("cp.async.cg.shared.global [%0], [%1], 16;" :: "r"(SADDR), "l"(GPTR))
#define CP_COMMIT() asm volatile("cp.async.commit_group;" ::: "memory")
#define CP_WAIT(N)  asm volatile("cp.async.wait_group %0;" :: "n"(N) : "memory")
#define LDSM4(R, ADDR) \
    asm volatile("ldmatrix.sync.aligned.m8n8.x4.shared.b16 {%0,%1,%2,%3}, [%4];" \
        : "=r"((R)[0]), "=r"((R)[1]), "=r"((R)[2]), "=r"((R)[3]) : "r"(ADDR))
#define MMAF16(C, A, B0, B1) \
    asm volatile("mma.sync.aligned.m16n8k16.row.col.f32.f16.f16.f32 " \
        "{%0,%1,%2,%3}, {%4,%5,%6,%7}, {%8,%9}, {%0,%1,%2,%3};" \
        : "+f"((C)[0]), "+f"((C)[1]), "+f"((C)[2]), "+f"((C)[3]) \
        : "r"((A)[0]), "r"((A)[1]), "r"((A)[2]), "r"((A)[3]), "r"(B0), "r"(B1))

__device__ __forceinline__ void h8_to_f8(const uint4& r, float* f) {
    const __half2* hp = reinterpret_cast<const __half2*>(&r);
#pragma unroll
    for (int i = 0; i < 4; i++) {
        float2 t = __half22float2(hp[i]);
        f[2 * i] = t.x; f[2 * i + 1] = t.y;
    }
}

// ---------------- CSR build ------------------------------------------------
__global__ void k_count(const int* __restrict__ edge_index) {
    int e = blockIdx.x * blockDim.x + threadIdx.x;
    if (e < EE) atomicAdd(&g_deg[edge_index[EE + e]], 1);
}

__global__ void k_scan() {
    __shared__ int wsums[32];
    __shared__ int carry_s;
    int tid = threadIdx.x, lane = tid & 31, w = tid >> 5;
    if (tid == 0) carry_s = 0;
    __syncthreads();
    for (int base = 0; base < NN; base += 4096) {
        int i0 = base + tid * 4;
        int v[4];
        if (i0 + 4 <= NN) {
            int4 q = *(const int4*)(g_deg + i0);
            v[0] = q.x; v[1] = q.y; v[2] = q.z; v[3] = q.w;
        } else {
#pragma unroll
            for (int j = 0; j < 4; j++) v[j] = (i0 + j < NN) ? g_deg[i0 + j] : 0;
        }
        int tsum = v[0] + v[1] + v[2] + v[3];
        int inc = tsum;
#pragma unroll
        for (int o = 1; o < 32; o <<= 1) {
            int t = __shfl_up_sync(0xffffffffu, inc, o);
            if (lane >= o) inc += t;
        }
        if (lane == 31) wsums[w] = inc;
        __syncthreads();
        if (w == 0) {
            int ws = wsums[lane];
#pragma unroll
            for (int o = 1; o < 32; o <<= 1) {
                int t = __shfl_up_sync(0xffffffffu, ws, o);
                if (lane >= o) ws += t;
            }
            wsums[lane] = ws;
        }
        __syncthreads();
        int offset = carry_s + (w ? wsums[w - 1] : 0) + inc - tsum;
        int e0 = offset, e1 = e0 + v[0], e2 = e1 + v[1], e3 = e2 + v[2];
        if (i0 < NN)     { g_rowptr[i0]     = e0; g_wptr[i0]     = e0; }
        if (i0 + 1 < NN) { g_rowptr[i0 + 1] = e1; g_wptr[i0 + 1] = e1; }
        if (i0 + 2 < NN) { g_rowptr[i0 + 2] = e2; g_wptr[i0 + 2] = e2; }
        if (i0 + 3 < NN) { g_rowptr[i0 + 3] = e3; g_wptr[i0 + 3] = e3; }
        __syncthreads();
        if (tid == 1023) carry_s = offset + tsum;
        __syncthreads();
    }
    if (tid == 0) g_rowptr[NN] = carry_s;
}

__global__ void k_scatter(const int* __restrict__ edge_index) {
    int e = blockIdx.x * blockDim.x + threadIdx.x;
    if (e < EE) {
        int src = edge_index[e];
        int dst = edge_index[EE + e];
        g_col[atomicAdd(&g_wptr[dst], 1)] = src;
    }
}

// ---------------- fused fp16 prep: x cvt + W1t + W2t -----------------------
#define NXCHUNK (NPAD * FIN / 4)
__global__ void k_prep(const float* __restrict__ x, const float* __restrict__ W1f,
                       const float* __restrict__ W2f)
{
    int t = blockIdx.x * blockDim.x + threadIdx.x;
    if (t < NXCHUNK) {
        int base = t * 4;
        int row = base >> 7;
        float4 v = (row < NN) ? *(const float4*)(x + base) : make_float4(0.f, 0.f, 0.f, 0.f);
        __half2 h0 = __floats2half2_rn(v.x, v.y);
        __half2 h1 = __floats2half2_rn(v.z, v.w);
        *(uint2*)(g_xh + base) = make_uint2(*(unsigned*)&h0, *(unsigned*)&h1);
    } else {
        int u = t - NXCHUNK;
        if (u < 256 * FIN) {
            int n = u / FIN, k = u - n * FIN;
            g_w1t[u] = __float2half_rn(W1f[k * 256 + n]);
        } else if (u < 256 * FIN + 256 * H1) {
            int v2 = u - 256 * FIN;
            int n = v2 / H1, k = v2 - n * H1;
            g_w2t[v2] = __float2half_rn(W2f[k * 256 + n]);
        }
    }
}

// ---------------- fp16 HMMA GEMM, fp16 C, fused al epilogue ----------------
#define MBUF 10240
#define MSTAGE (2 * MBUF)
#define MSM_TOTAL (2 * MSTAGE)

__device__ __forceinline__ void stage_chunk(
    uint32_t sb32, int rbase, int nbase, int k0, int K, int tid,
    const __half* __restrict__ A, const __half* __restrict__ B)
{
#pragma unroll
    for (int t = tid; t < 512; t += 256) {
        int r = t >> 2, seg = t & 3;
        uint32_t so = sb32 + r * 80 + seg * 16;
        CP16(so,        A + (size_t)(rbase + r) * K + k0 + seg * 8);
        CP16(so + MBUF, B + (size_t)(nbase + r) * K + k0 + seg * 8);
    }
}

template<int FOLD>
__global__ __launch_bounds__(256)
void k_mmagemm(const __half* __restrict__ A, const __half* __restrict__ B,
               __half* __restrict__ C, int K,
               const float* __restrict__ avs, const float* __restrict__ avd,
               float* __restrict__ foldS, float* __restrict__ foldD)
{
    extern __shared__ char sm[];
    uint32_t smb = smem_u32(sm);
    int tid = threadIdx.x, lane = tid & 31, wid = tid >> 5;
    int rbase = blockIdx.x * 128, nbase = blockIdx.y * 128;
    int wm = (wid >> 2) * 64, wn = (wid & 3) * 32;

    float acc[4][4][4];
#pragma unroll
    for (int i = 0; i < 4; i++)
#pragma unroll
        for (int j = 0; j < 4; j++)
#pragma unroll
            for (int q = 0; q < 4; q++) acc[i][j][q] = 0.f;

    int nch = K >> 5;
    stage_chunk(smb, rbase, nbase, 0, K, tid, A, B);
    CP_COMMIT();

    int row = lane & 15, kh = lane >> 4;
    for (int ch = 0; ch < nch; ch++) {
        if (ch + 1 < nch) {
            stage_chunk(smb + ((ch + 1) & 1) * MSTAGE, rbase, nbase, (ch + 1) << 5, K, tid, A, B);
            CP_COMMIT();
            CP_WAIT(1);
        } else {
            CP_WAIT(0);
        }
        __syncthreads();

        uint32_t s0 = smb + (ch & 1) * MSTAGE;
#pragma unroll
        for (int s = 0; s < 2; s++) {
            int colb = (s * 16 + kh * 8) * 2;
            uint32_t ah[4][4], bh[2][4];
#pragma unroll
            for (int mi = 0; mi < 4; mi++)
                LDSM4(ah[mi], s0 + (wm + mi * 16 + row) * 80 + colb);
#pragma unroll
            for (int bi = 0; bi < 2; bi++)
                LDSM4(bh[bi], s0 + MBUF + (wn + bi * 16 + row) * 80 + colb);
#pragma unroll
            for (int mi = 0; mi < 4; mi++)
#pragma unroll
                for (int ni = 0; ni < 4; ni++) {
                    int bi = ni >> 1, hf = ni & 1;
                    MMAF16(acc[mi][ni], ah[mi], bh[bi][hf], bh[bi][hf + 2]);
                }
        }
        __syncthreads();
    }

#pragma unroll
    for (int mi = 0; mi < 4; mi++)
#pragma unroll
        for (int ni = 0; ni < 4; ni++) {
            int r0 = rbase + wm + mi * 16 + (lane >> 2);
            int c  = nbase + wn + ni * 8 + (lane & 3) * 2;
            __half* p = C + (size_t)r0 * 256 + c;
            *(__half2*)p = __floats2half2_rn(acc[mi][ni][0], acc[mi][ni][1]);
            *(__half2*)(p + 8 * 256) = __floats2half2_rn(acc[mi][ni][2], acc[mi][ni][3]);
        }

    // fused attention-logit fold
    {
        int h = (nbase + wn) >> 5;
        int slot = blockIdx.y * 4 + (wid & 3);
#pragma unroll
        for (int mi = 0; mi < 4; mi++) {
            float ps0 = 0.f, ps1 = 0.f, pd0 = 0.f, pd1 = 0.f;
#pragma unroll
            for (int ni = 0; ni < 4; ni++) {
                int cc = ni * 8 + (lane & 3) * 2;
                float s0, s1, d0, d1;
                if (FOLD == 1) {
                    s0 = avs[h * 32 + cc]; s1 = avs[h * 32 + cc + 1];
                    d0 = avd[h * 32 + cc]; d1 = avd[h * 32 + cc + 1];
                } else {
                    int c = nbase + wn + cc;
                    s0 = avs[c]; s1 = avs[c + 1];
                    d0 = avd[c]; d1 = avd[c + 1];
                }
                ps0 += acc[mi][ni][0] * s0 + acc[mi][ni][1] * s1;
                ps1 += acc[mi][ni][2] * s0 + acc[mi][ni][3] * s1;
                pd0 += acc[mi][ni][0] * d0 + acc[mi][ni][1] * d1;
                pd1 += acc[mi][ni][2] * d0 + acc[mi][ni][3] * d1;
            }
#pragma unroll
            for (int o = 1; o <= 2; o <<= 1) {
                ps0 += __shfl_xor_sync(0xffffffffu, ps0, o);
                ps1 += __shfl_xor_sync(0xffffffffu, ps1, o);
                pd0 += __shfl_xor_sync(0xffffffffu, pd0, o);
                pd1 += __shfl_xor_sync(0xffffffffu, pd1, o);
            }
            if ((lane & 3) == 0) {
                int r0 = rbase + wm + mi * 16 + (lane >> 2);
                if (FOLD == 1) {
                    foldS[(size_t)r0 * 8 + h] = ps0;
                    foldS[(size_t)(r0 + 8) * 8 + h] = ps1;
                    foldD[(size_t)r0 * 8 + h] = pd0;
                    foldD[(size_t)(r0 + 8) * 8 + h] = pd1;
                } else {
                    foldS[(size_t)slot * NPAD + r0] = ps0;
                    foldS[(size_t)slot * NPAD + r0 + 8] = ps1;
                    foldD[(size_t)slot * NPAD + r0] = pd0;
                    foldD[(size_t)slot * NPAD + r0 + 8] = pd1;
                }
            }
        }
    }
}

// sum the 8 layer-2 al partial slots (deterministic)
__global__ void k_alsum2()
{
    int i = blockIdx.x * blockDim.x + threadIdx.x;
    if (i >= NN) return;
    float s = 0.f, d = 0.f;
#pragma unroll
    for (int k = 0; k < 8; k++) {
        s += g_alpS[(size_t)k * NPAD + i];
        d += g_alpD[(size_t)k * NPAD + i];
    }
    g_als2[i] = s;
    g_ald2[i] = d;
}

// ---------------- warp-per-node softmax aggregation (fp16 gather) ----------
template<int H, bool ELU, bool FININV>
__global__ __launch_bounds__(256)
void k_agg_w(const __half* __restrict__ xw, const float* __restrict__ als,
             const float* __restrict__ ald, const float* __restrict__ bias,
             __half* __restrict__ outh, float* __restrict__ ssout)
{
    int gw = (blockIdx.x * blockDim.x + threadIdx.x) >> 5;
    int lane = threadIdx.x & 31;
    if (gw >= NN) return;
    int n = gw;
    int beg = g_rowptr[n];
    int deg = g_rowptr[n + 1] - beg;

    const int myh = (lane * H) >> 5;
    const float admy = ald[(size_t)n * H + myh];

    float eself = als[(size_t)n * H + myh] + admy;
    eself = eself > 0.f ? eself : NEG_SLOPE * eself;
    float exs = __expf(eself);
    float den = exs;

    float acc[8];
    {
        uint4 raw = *(const uint4*)(xw + (size_t)n * 256 + (lane << 3));
        float f[8]; h8_to_f8(raw, f);
#pragma unroll
        for (int t = 0; t < 8; t++) acc[t] = exs * f[t];
    }

    for (int base = 0; base < deg; base += 32) {
        int idx = base + lane;
        int scol = (idx < deg) ? g_col[beg + idx] : 0;
        int cn = min(32, deg - base);
#pragma unroll 4
        for (int jj = 0; jj < cn; jj++) {
            int s = __shfl_sync(0xffffffffu, scol, jj);
            float e = als[(size_t)s * H + myh] + admy;
            e = e > 0.f ? e : NEG_SLOPE * e;
            float ex = __expf(e);
            den += ex;
            uint4 raw = *(const uint4*)(xw + (size_t)s * 256 + (lane << 3));
            float f[8]; h8_to_f8(raw, f);
#pragma unroll
            for (int t = 0; t < 8; t++) acc[t] += ex * f[t];
        }
    }

    float invd = 1.f / den;
    const float4* bb = (const float4*)(bias + (lane << 3));
    float4 b0 = bb[0], b1 = bb[1];
    float o[8];
    o[0] = acc[0] * invd + b0.x; o[1] = acc[1] * invd + b0.y;
    o[2] = acc[2] * invd + b0.z; o[3] = acc[3] * invd + b0.w;
    o[4] = acc[4] * invd + b1.x; o[5] = acc[5] * invd + b1.y;
    o[6] = acc[6] * invd + b1.z; o[7] = acc[7] * invd + b1.w;
    float ssq = 0.f;
#pragma unroll
    for (int t = 0; t < 8; t++) {
        if (ELU) o[t] = o[t] > 0.f ? o[t] : expm1f(o[t]);
        ssq += o[t] * o[t];
    }
    {
        uint4 ho;
        __half2* hp = (__half2*)&ho;
        hp[0] = __floats2half2_rn(o[0], o[1]);
        hp[1] = __floats2half2_rn(o[2], o[3]);
        hp[2] = __floats2half2_rn(o[4], o[5]);
        hp[3] = __floats2half2_rn(o[6], o[7]);
        *(uint4*)(outh + (size_t)n * 256 + (lane << 3)) = ho;
    }
#pragma unroll
    for (int oo = 16; oo; oo >>= 1) ssq += __shfl_xor_sync(0xffffffffu, ssq, oo);
    if (lane == 0) {
        if (FININV) g_inv[n] = 1.f / fmaxf(sqrtf(ssout[n] + ssq), 1e-8f);
        else        ssout[n] = ssq;
    }
}

// ---------------- contrastive loss: block per walk + last-block reduce -----
#define SMEM_EMB_F4 (WALK_LEN * 128)
#define SMEM_LOSS_BYTES (SMEM_EMB_F4 * 16 + WALK_LEN * 4 + WALK_LEN * 4 + 16 * 4)

__device__ __forceinline__ float dot16(const float4& a0, const float4& a1,
                                       const float4& a2, const float4& a3,
                                       const float4& p0, const float4& p1,
                                       const float4& p2, const float4& p3)
{
    float s = a0.x * p0.x + a0.y * p0.y + a0.z * p0.z + a0.w * p0.w
            + a1.x * p1.x + a1.y * p1.y + a1.z * p1.z + a1.w * p1.w
            + a2.x * p2.x + a2.y * p2.y + a2.z * p2.z + a2.w * p2.w
            + a3.x * p3.x + a3.y * p3.y + a3.z * p3.z + a3.w * p3.w;
#pragma unroll
    for (int o = 16; o; o >>= 1) s += __shfl_xor_sync(0xffffffffu, s, o);
    return s;
}
__device__ __forceinline__ float4 h4_to_f4(uint2 r) {
    const __half2* hp = reinterpret_cast<const __half2*>(&r);
    float2 a = __half22float2(hp[0]), b = __half22float2(hp[1]);
    return make_float4(a.x, a.y, b.x, b.y);
}

__global__ __launch_bounds__(512)
void k_loss(const int* __restrict__ walks, const int* __restrict__ negs,
            float* __restrict__ out)
{
    extern __shared__ char smraw[];
    float4* sm4   = (float4*)smraw;
    int*    ids_s = (int*)(smraw + SMEM_EMB_F4 * 16);
    float*  inv_s = (float*)(smraw + SMEM_EMB_F4 * 16 + WALK_LEN * 4);
    float*  wsum  = (float*)(smraw + SMEM_EMB_F4 * 16 + WALK_LEN * 8);
    __shared__ int s_last;

    int b = blockIdx.x;
    int tid = threadIdx.x, lane = tid & 31, w = tid >> 5;

    if (tid < WALK_LEN) {
        int id = walks[b * WALK_LEN + tid];
        ids_s[tid] = id;
        inv_s[tid] = g_inv[id];
    }
    __syncthreads();

    for (int f = tid; f < WALK_LEN * 64; f += 512) {
        int r = f >> 6, q = f & 63;
        int id = ids_s[r];
        float iv = inv_s[r];
        uint4 raw = (q < 32) ? *(const uint4*)(g_e1h + (size_t)id * 256 + q * 8)
                             : *(const uint4*)(g_e2h + (size_t)id * 256 + (q - 32) * 8);
        float fv[8]; h8_to_f8(raw, fv);
        sm4[r * 128 + 2 * q]     = make_float4(fv[0] * iv, fv[1] * iv, fv[2] * iv, fv[3] * iv);
        sm4[r * 128 + 2 * q + 1] = make_float4(fv[4] * iv, fv[5] * iv, fv[6] * iv, fv[7] * iv);
    }
    __syncthreads();

    float term_acc = 0.f;
    for (int k = 0; k < 4; k++) {
        int l = (w << 2) | k;
        const float4* ar = sm4 + (size_t)l * 128;
        float4 A0 = ar[lane], A1 = ar[32 + lane], A2 = ar[64 + lane], A3 = ar[96 + lane];

        int posid[2 * WINDOW];
        bool pval[2 * WINDOW];
        float pos_sum = 0.f;
#pragma unroll
        for (int p = 0; p < 2 * WINDOW; p++) {
            int off = (p < WINDOW) ? (p - WINDOW) : (p - WINDOW + 1);
            int pp = l + off;
            bool val = (pp >= 0) && (pp < WALK_LEN);
            int ppc = min(max(pp, 0), WALK_LEN - 1);
            pval[p] = val;
            posid[p] = ids_s[ppc];
            const float4* pr = sm4 + (size_t)ppc * 128;
            float4 P0 = pr[lane], P1 = pr[32 + lane], P2 = pr[64 + lane], P3 = pr[96 + lane];
            float d = dot16(A0, A1, A2, A3, P0, P1, P2, P3);
            if (val) pos_sum += __expf(d * INV_TEMP);
        }

        int nbase = (b * WALK_LEN + l) * NEG_S;
        int ngl = (lane < NEG_S) ? negs[nbase + lane] : 0;
        float neg_sum = 0.f;
#pragma unroll
        for (int s = 0; s < NEG_S; s++) {
            int ng = __shfl_sync(0xffffffffu, ngl, s);
            bool inpos = false;
#pragma unroll
            for (int p = 0; p < 2 * WINDOW; p++)
                inpos = inpos || (pval[p] && (ng == posid[p]));
            const __half* n1 = g_e1h + (size_t)ng * 256;
            const __half* n2 = g_e2h + (size_t)ng * 256;
            float4 P0 = h4_to_f4(*(const uint2*)(n1 + 4 * lane));
            float4 P1 = h4_to_f4(*(const uint2*)(n1 + 128 + 4 * lane));
            float4 P2 = h4_to_f4(*(const uint2*)(n2 + 4 * lane));
            float4 P3 = h4_to_f4(*(const uint2*)(n2 + 128 + 4 * lane));
            float d = dot16(A0, A1, A2, A3, P0, P1, P2, P3);
            float sim = d * g_inv[ng] * INV_TEMP;
            if (!inpos) neg_sum += __expf(sim);
        }
        term_acc += log1pf(neg_sum / pos_sum);
    }

    if (lane == 0) wsum[w] = term_acc;
    __syncthreads();
    if (w == 0) {
        float s = (lane < 16) ? wsum[lane] : 0.f;
#pragma unroll
        for (int o = 16; o; o >>= 1) s += __shfl_xor_sync(0xffffffffu, s, o);
        if (lane == 0) g_terms[b] = s;
    }

    // last-block deterministic reduction (ticket self-resets for graph replay)
    if (tid == 0) {
        __threadfence();
        unsigned t = atomicAdd(&g_done, 1u);
        s_last = (t == NUM_WALKS - 1);
    }
    __syncthreads();
    if (s_last) {
        __threadfence();
        float v = g_terms[tid];           // blockDim == NUM_WALKS == 512
        wsum[0] = 0.f;                    // reuse smem via block reduce below
        __syncthreads();
        __shared__ float red[512];
        red[tid] = v;
        __syncthreads();
        for (int o = 256; o; o >>= 1) {
            if (tid < o) red[tid] += red[tid + o];
            __syncthreads();
        }
        if (tid == 0) { out[0] = red[0]; g_done = 0; }
    }
}

// ---------------- driver ---------------------------------------------------
extern "C" void kernel_launch(void* const* d_in, const int* in_sizes, int n_in,
                              void* d_out, int out_size)
{
    const float* x          = (const float*)d_in[0];
    const int*   edge_index = (const int*)  d_in[1];
    const int*   walks      = (const int*)  d_in[2];
    const int*   negs       = (const int*)  d_in[3];
    const float* W1         = (const float*)d_in[4];
    const float* a_src1     = (const float*)d_in[5];
    const float* a_dst1     = (const float*)d_in[6];
    const float* b1         = (const float*)d_in[7];
    const float* W2         = (const float*)d_in[8];
    const float* a_src2     = (const float*)d_in[9];
    const float* a_dst2     = (const float*)d_in[10];
    const float* b2         = (const float*)d_in[11];
    float* out = (float*)d_out;

    float *als1, *ald1, *als2, *ald2, *ss1, *alpS, *alpD;
    __half *xh, *w1t, *w2t, *xw1h, *xw2h, *e1h, *e2h;
    void* degp;
    cudaGetSymbolAddress((void**)&xh,   g_xh);
    cudaGetSymbolAddress((void**)&w1t,  g_w1t);
    cudaGetSymbolAddress((void**)&w2t,  g_w2t);
    cudaGetSymbolAddress((void**)&xw1h, g_xw1h);
    cudaGetSymbolAddress((void**)&xw2h, g_xw2h);
    cudaGetSymbolAddress((void**)&e1h,  g_e1h);
    cudaGetSymbolAddress((void**)&e2h,  g_e2h);
    cudaGetSymbolAddress((void**)&als1, g_als1);
    cudaGetSymbolAddress((void**)&ald1, g_ald1);
    cudaGetSymbolAddress((void**)&als2, g_als2);
    cudaGetSymbolAddress((void**)&ald2, g_ald2);
    cudaGetSymbolAddress((void**)&alpS, g_alpS);
    cudaGetSymbolAddress((void**)&alpD, g_alpD);
    cudaGetSymbolAddress((void**)&ss1,  g_ss1);
    cudaGetSymbolAddress(&degp, g_deg);

    static cudaStream_t s2 = nullptr;
    static cudaEvent_t evF = nullptr, evJ = nullptr;
    static int attr_set = 0;
    if (!attr_set) {
        cudaFuncSetAttribute(k_loss, cudaFuncAttributeMaxDynamicSharedMemorySize,
                             SMEM_LOSS_BYTES);
        cudaFuncSetAttribute(k_mmagemm<1>, cudaFuncAttributeMaxDynamicSharedMemorySize,
                             MSM_TOTAL);
        cudaFuncSetAttribute(k_mmagemm<2>, cudaFuncAttributeMaxDynamicSharedMemorySize,
                             MSM_TOTAL);
        cudaStreamCreateWithFlags(&s2, cudaStreamNonBlocking);
        cudaEventCreateWithFlags(&evF, cudaEventDisableTiming);
        cudaEventCreateWithFlags(&evJ, cudaEventDisableTiming);
        attr_set = 1;
    }

    // ---- fork: CSR build on s2, prep + GEMM1 on main stream ---------------
    cudaEventRecord(evF, 0);
    cudaStreamWaitEvent(s2, evF, 0);

    cudaMemsetAsync(degp, 0, NN * sizeof(int), s2);
    k_count<<<(EE + 255) / 256, 256, 0, s2>>>(edge_index);
    k_scan<<<1, 1024, 0, s2>>>();
    k_scatter<<<(EE + 255) / 256, 256, 0, s2>>>(edge_index);
    cudaEventRecord(evJ, s2);

    k_prep<<<(NXCHUNK + 256 * (FIN + H1) + 255) / 256, 256>>>(x, W1, W2);
    k_mmagemm<1><<<dim3(NPAD / 128, 2), 256, MSM_TOTAL>>>(
        xh, w1t, xw1h, FIN, a_src1, a_dst1, als1, ald1);

    // ---- join --------------------------------------------------------------
    cudaStreamWaitEvent(0, evJ, 0);

    // layer 1 aggregation (emb1 -> e1h, also GEMM2's A operand)
    k_agg_w<NHEADS, true, false><<<(NN * 32 + 255) / 256, 256>>>(
        xw1h, als1, ald1, b1, e1h, ss1);

    // layer 2
    k_mmagemm<2><<<dim3(NPAD / 128, 2), 256, MSM_TOTAL>>>(
        e1h, w2t, xw2h, H1, a_src2, a_dst2, alpS, alpD);
    k_alsum2<<<(NN + 255) / 256, 256>>>();
    k_agg_w<1, false, true><<<(NN * 32 + 255) / 256, 256>>>(
        xw2h, als2, ald2, b2, e2h, ss1);

    // loss (+ fused final reduction)
    k_loss<<<NUM_WALKS, 512, SMEM_LOSS_BYTES>>>(walks, negs, out);
}